// round 1
// baseline (speedup 1.0000x reference)
#include <cuda_runtime.h>
#include <cuda_bf16.h>

// Problem constants
#define DIMC   512
#define HEADS  8
#define WIN    128
#define HD     64
#define NTOK   65536          // 16*4096
#define NWIN   512            // NTOK/WIN
#define BH     (NWIN*HEADS)   // 4096

// Scratch (device globals: allocation-free rule)
__device__ float g_q[(size_t)BH * WIN * HD];
__device__ float g_k[(size_t)BH * WIN * HD];
__device__ float g_v[(size_t)BH * WIN * HD];
__device__ float g_o[(size_t)NTOK * DIMC];

// ---------------------------------------------------------------------------
// Tiled fp32 GEMM: C[m,n] = sum_k A[m,k] * B[n,k]   (A:[M,512], B:[N,512])
// BM=BN=128, BK=16, 256 threads, 8x8 per thread (split 4+4 quadrants).
// MODE 0: A = x, B = w_qkv; epilogue scatters into g_q/g_k/g_v ([win,h,t,d]).
// MODE 1: A = g_o, B = w_proj; epilogue adds bias, writes C (d_out).
// ---------------------------------------------------------------------------
template<int MODE>
__global__ void __launch_bounds__(256, 2)
gemm128(const float* __restrict__ Ain, const float* __restrict__ B,
        const float* __restrict__ bias, float* __restrict__ C)
{
    const float* A = (MODE == 0) ? Ain : g_o;

    __shared__ float As[16][128];
    __shared__ float Bs[16][128];

    const int tid = threadIdx.x;
    const int tx  = tid & 15;
    const int ty  = tid >> 4;
    const int m0  = blockIdx.y * 128;
    const int n0  = blockIdx.x * 128;

    // loader mapping: each thread loads rows (lr, lr+64), 4 consecutive k's
    const int lr = tid >> 2;          // 0..63
    const int lc = (tid & 3) * 4;     // 0,4,8,12

    float acc[8][8];
#pragma unroll
    for (int i = 0; i < 8; ++i)
#pragma unroll
        for (int j = 0; j < 8; ++j) acc[i][j] = 0.0f;

    float4 va0, va1, vb0, vb1;

#define LOADG(kt)                                                              \
    do {                                                                       \
        const int kb = (kt) * 16 + lc;                                         \
        va0 = *(const float4*)&A[(size_t)(m0 + lr)      * 512 + kb];           \
        va1 = *(const float4*)&A[(size_t)(m0 + lr + 64) * 512 + kb];           \
        vb0 = *(const float4*)&B[(size_t)(n0 + lr)      * 512 + kb];           \
        vb1 = *(const float4*)&B[(size_t)(n0 + lr + 64) * 512 + kb];           \
    } while (0)

#define STORES()                                                               \
    do {                                                                       \
        As[lc + 0][lr] = va0.x; As[lc + 1][lr] = va0.y;                        \
        As[lc + 2][lr] = va0.z; As[lc + 3][lr] = va0.w;                        \
        As[lc + 0][lr + 64] = va1.x; As[lc + 1][lr + 64] = va1.y;              \
        As[lc + 2][lr + 64] = va1.z; As[lc + 3][lr + 64] = va1.w;              \
        Bs[lc + 0][lr] = vb0.x; Bs[lc + 1][lr] = vb0.y;                        \
        Bs[lc + 2][lr] = vb0.z; Bs[lc + 3][lr] = vb0.w;                        \
        Bs[lc + 0][lr + 64] = vb1.x; Bs[lc + 1][lr + 64] = vb1.y;              \
        Bs[lc + 2][lr + 64] = vb1.z; Bs[lc + 3][lr + 64] = vb1.w;              \
    } while (0)

    LOADG(0);
    STORES();
    __syncthreads();

    const int T = 512 / 16;  // 32 k-tiles
    for (int t = 0; t < T; ++t) {
        if (t + 1 < T) LOADG(t + 1);

#pragma unroll
        for (int k = 0; k < 16; ++k) {
            float4 a0 = *(const float4*)&As[k][ty * 4];
            float4 a1 = *(const float4*)&As[k][64 + ty * 4];
            float4 b0 = *(const float4*)&Bs[k][tx * 4];
            float4 b1 = *(const float4*)&Bs[k][64 + tx * 4];
            float a[8] = {a0.x, a0.y, a0.z, a0.w, a1.x, a1.y, a1.z, a1.w};
            float b[8] = {b0.x, b0.y, b0.z, b0.w, b1.x, b1.y, b1.z, b1.w};
#pragma unroll
            for (int i = 0; i < 8; ++i)
#pragma unroll
                for (int j = 0; j < 8; ++j)
                    acc[i][j] += a[i] * b[j];
        }
        __syncthreads();
        if (t + 1 < T) {
            STORES();
            __syncthreads();
        }
    }
#undef LOADG
#undef STORES

    // epilogue
#pragma unroll
    for (int ii = 0; ii < 8; ++ii) {
        const int m = m0 + ((ii >> 2) * 64) + ty * 4 + (ii & 3);
#pragma unroll
        for (int jj = 0; jj < 8; ++jj) {
            const int n = n0 + ((jj >> 2) * 64) + tx * 4 + (jj & 3);
            const float v = acc[ii][jj];
            if (MODE == 0) {
                const int s   = n >> 9;          // 0:q 1:k 2:v
                const int h   = (n >> 6) & 7;
                const int d   = n & 63;
                const int win = m >> 7;
                const int tt  = m & 127;
                const size_t idx = (((size_t)(win * HEADS + h) * WIN) + tt) * HD + d;
                float* dst = (s == 0) ? g_q : ((s == 1) ? g_k : g_v);
                dst[idx] = v;
            } else {
                C[(size_t)m * 512 + n] = v + bias[n];
            }
        }
    }
}

// ---------------------------------------------------------------------------
// Attention: one CTA per (window, head). Q,K,V: [128,64] fp32.
// S = Q K^T * 0.125, causal mask, softmax, O = P V -> g_o token-major.
// smem: Qt/Kt transposed [64][129] (pad -> conflict-free), Vs [128][64],
// Ss [128][132] (pad -> 2-way max in softmax).
// ---------------------------------------------------------------------------
#define QT_STRIDE 129
#define SS_STRIDE 132
#define ATTN_SMEM ((64 * QT_STRIDE * 2 + 128 * 64 + 128 * SS_STRIDE) * 4)

__global__ void __launch_bounds__(256)
attn128()
{
    extern __shared__ float sm[];
    float* Qt = sm;                          // [64][129] (Qt[d][t])
    float* Kt = Qt + 64 * QT_STRIDE;         // [64][129]
    float* Vs = Kt + 64 * QT_STRIDE;         // [128][64] row-major
    float* Ss = Vs + 128 * 64;               // [128][132]

    const int bh  = blockIdx.x;
    const int tid = threadIdx.x;
    const float* qg = g_q + (size_t)bh * (WIN * HD);
    const float* kg = g_k + (size_t)bh * (WIN * HD);
    const float* vg = g_v + (size_t)bh * (WIN * HD);

    for (int i = tid; i < WIN * HD; i += 256) {
        const int t = i >> 6, d = i & 63;
        Qt[d * QT_STRIDE + t] = qg[i];
        Kt[d * QT_STRIDE + t] = kg[i];
        Vs[i] = vg[i];
    }
    __syncthreads();

    const int tx = tid & 15, ty = tid >> 4;

    // ---- S = Q K^T ----
    float acc[8][8];
#pragma unroll
    for (int i = 0; i < 8; ++i)
#pragma unroll
        for (int j = 0; j < 8; ++j) acc[i][j] = 0.0f;

#pragma unroll 4
    for (int kk = 0; kk < 64; ++kk) {
        float a[8], b[8];
#pragma unroll
        for (int i = 0; i < 4; ++i) {
            a[i]     = Qt[kk * QT_STRIDE + ty * 4 + i];
            a[4 + i] = Qt[kk * QT_STRIDE + 64 + ty * 4 + i];
            b[i]     = Kt[kk * QT_STRIDE + tx * 4 + i];
            b[4 + i] = Kt[kk * QT_STRIDE + 64 + tx * 4 + i];
        }
#pragma unroll
        for (int i = 0; i < 8; ++i)
#pragma unroll
            for (int j = 0; j < 8; ++j)
                acc[i][j] += a[i] * b[j];
    }

    // scale + causal mask + store to smem
#pragma unroll
    for (int ii = 0; ii < 8; ++ii) {
        const int r = ((ii >> 2) * 64) + ty * 4 + (ii & 3);
#pragma unroll
        for (int jj = 0; jj < 8; ++jj) {
            const int c = ((jj >> 2) * 64) + tx * 4 + (jj & 3);
            Ss[r * SS_STRIDE + c] = (c <= r) ? acc[ii][jj] * 0.125f : -1e30f;
        }
    }
    __syncthreads();

    // ---- softmax: 2 threads per row ----
    {
        const int row = tid >> 1, half = tid & 1;
        float* srow = Ss + row * SS_STRIDE + half * 64;
        float m = -1e30f;
#pragma unroll 8
        for (int j = 0; j < 64; ++j) m = fmaxf(m, srow[j]);
        m = fmaxf(m, __shfl_xor_sync(0xffffffffu, m, 1));
        float s = 0.0f;
#pragma unroll 8
        for (int j = 0; j < 64; ++j) {
            const float e = __expf(srow[j] - m);
            srow[j] = e;
            s += e;
        }
        s += __shfl_xor_sync(0xffffffffu, s, 1);
        const float inv = 1.0f / s;
#pragma unroll 8
        for (int j = 0; j < 64; ++j) srow[j] *= inv;
    }
    __syncthreads();

    // ---- O = P V : 8 rows x 4 cols per thread ----
    float o[8][4];
#pragma unroll
    for (int i = 0; i < 8; ++i)
#pragma unroll
        for (int j = 0; j < 4; ++j) o[i][j] = 0.0f;

#pragma unroll 2
    for (int kk = 0; kk < 128; ++kk) {
        const float4 bv = *(const float4*)&Vs[kk * 64 + tx * 4];
        const float b4[4] = {bv.x, bv.y, bv.z, bv.w};
        float a[8];
#pragma unroll
        for (int i = 0; i < 4; ++i) {
            a[i]     = Ss[(ty * 4 + i) * SS_STRIDE + kk];
            a[4 + i] = Ss[(64 + ty * 4 + i) * SS_STRIDE + kk];
        }
#pragma unroll
        for (int i = 0; i < 8; ++i)
#pragma unroll
            for (int j = 0; j < 4; ++j)
                o[i][j] += a[i] * b4[j];
    }

    const int win = bh >> 3, h = bh & 7;
#pragma unroll
    for (int ii = 0; ii < 8; ++ii) {
        const int r = ((ii >> 2) * 64) + ty * 4 + (ii & 3);
        float4 val = make_float4(o[ii][0], o[ii][1], o[ii][2], o[ii][3]);
        *(float4*)&g_o[((size_t)(win * WIN + r) * DIMC) + h * HD + tx * 4] = val;
    }
}

// ---------------------------------------------------------------------------
extern "C" void kernel_launch(void* const* d_in, const int* in_sizes, int n_in,
                              void* d_out, int out_size)
{
    const float* x      = (const float*)d_in[0];  // [16,4096,512]
    const float* w_qkv  = (const float*)d_in[1];  // [1536,512]
    const float* w_proj = (const float*)d_in[2];  // [512,512]
    const float* b_proj = (const float*)d_in[3];  // [512]
    float* out = (float*)d_out;                   // [16,4096,512]

    // 1) fused QKV projection -> g_q/g_k/g_v
    dim3 g1(1536 / 128, NTOK / 128);
    gemm128<0><<<g1, 256>>>(x, w_qkv, nullptr, nullptr);

    // 2) per-(window,head) attention -> g_o
    cudaFuncSetAttribute(attn128, cudaFuncAttributeMaxDynamicSharedMemorySize,
                         ATTN_SMEM);
    attn128<<<BH, 256, ATTN_SMEM>>>();

    // 3) output projection + bias -> d_out
    dim3 g2(512 / 128, NTOK / 128);
    gemm128<1><<<g2, 256>>>(nullptr, w_proj, b_proj, out);
}

// round 3
// speedup vs baseline: 2.7881x; 2.7881x over previous
#include <cuda_runtime.h>
#include <cuda_fp16.h>
#include <cstdint>

// Problem constants
#define DIMC   512
#define HEADS  8
#define WIN    128
#define HD     64
#define NTOK   65536          // 16*4096
#define NWIN   512            // NTOK/WIN
#define BH     (NWIN*HEADS)   // 4096

// Scratch (device globals: allocation-free rule)
__device__ float  g_q[(size_t)BH * WIN * HD];     // fp32 q [win,h,t,d]
__device__ float  g_k[(size_t)BH * WIN * HD];
__device__ float  g_v[(size_t)BH * WIN * HD];
__device__ __half hx[(size_t)NTOK * DIMC];        // fp16 copy of x
__device__ __half hwqkv[(size_t)3 * DIMC * DIMC]; // fp16 w_qkv
__device__ __half hwproj[(size_t)DIMC * DIMC];    // fp16 w_proj
__device__ __half g_oh[(size_t)NTOK * DIMC];      // fp16 attention output

// ---------------------------------------------------------------------------
// helpers
// ---------------------------------------------------------------------------
__device__ __forceinline__ uint32_t s2u(const void* p) {
    uint32_t a;
    asm("{ .reg .u64 t; cvta.to.shared.u64 t, %1; cvt.u32.u64 %0, t; }"
        : "=r"(a) : "l"(p));
    return a;
}

__device__ __forceinline__ void cp16(uint32_t dst, const void* src) {
    asm volatile("cp.async.cg.shared.global [%0], [%1], 16;" :: "r"(dst), "l"(src));
}
#define CP_COMMIT() asm volatile("cp.async.commit_group;" ::: "memory")

__device__ __forceinline__ void ldsm_x4(uint32_t* r, uint32_t a) {
    asm volatile("ldmatrix.sync.aligned.m8n8.x4.shared.b16 {%0,%1,%2,%3}, [%4];"
        : "=r"(r[0]), "=r"(r[1]), "=r"(r[2]), "=r"(r[3]) : "r"(a));
}

__device__ __forceinline__ void mma_f16(float* d, const uint32_t* a,
                                        const uint32_t b0, const uint32_t b1) {
    asm volatile(
        "mma.sync.aligned.m16n8k16.row.col.f32.f16.f16.f32 "
        "{%0,%1,%2,%3}, {%4,%5,%6,%7}, {%8,%9}, {%0,%1,%2,%3};"
        : "+f"(d[0]), "+f"(d[1]), "+f"(d[2]), "+f"(d[3])
        : "r"(a[0]), "r"(a[1]), "r"(a[2]), "r"(a[3]), "r"(b0), "r"(b1));
}

// ---------------------------------------------------------------------------
// fp32 -> fp16 conversion (vectorized, 4 elems/thread)
// ---------------------------------------------------------------------------
__global__ void cvt_f2h(const float* __restrict__ src, __half* __restrict__ dst,
                        int n4)
{
    int i = blockIdx.x * blockDim.x + threadIdx.x;
    if (i < n4) {
        float4 v = ((const float4*)src)[i];
        __half2 h0 = __floats2half2_rn(v.x, v.y);
        __half2 h1 = __floats2half2_rn(v.z, v.w);
        ((__half2*)dst)[2 * i]     = h0;
        ((__half2*)dst)[2 * i + 1] = h1;
    }
}

// ---------------------------------------------------------------------------
// fp16 tensor-core GEMM: C[m,n] = sum_k A[m,k]*B[n,k], K=512.
// BM=BN=128, BK=64, 3-stage cp.async, 8 warps each 64x32 (m16n8k16).
// MODE 0: A=hx, B=hwqkv -> scatter fp32 into g_q/g_k/g_v [win,h,t,d]
// MODE 1: A=g_oh, B=hwproj, +bias -> fp32 C
// ---------------------------------------------------------------------------
#define PA_H 72                              // padded halfs per smem row (144B)
#define STG_BYTES (128 * PA_H * 2)           // 18432 per tile
#define GEMM_SMEM (3 * 2 * STG_BYTES)        // 110592

template<int MODE>
__global__ void __launch_bounds__(256, 1)
hgemm(float* __restrict__ C, const float* __restrict__ bias)
{
    extern __shared__ __align__(128) char smem[];
    const __half* Ag = (MODE == 0) ? hx : g_oh;
    const __half* Bg = (MODE == 0) ? hwqkv : hwproj;

    const uint32_t sb = s2u(smem);
    const int tid  = threadIdx.x;
    const int m0   = blockIdx.y * 128;
    const int n0   = blockIdx.x * 128;
    const int warp = tid >> 5, lane = tid & 31;
    const int wy   = warp >> 2, wx = warp & 3;   // warp tile: (wy*64, wx*32)

    float acc[16][4];                            // [mt*4+nt][c0..c3]
#pragma unroll
    for (int i = 0; i < 16; ++i)
#pragma unroll
        for (int j = 0; j < 4; ++j) acc[i][j] = 0.0f;

    // stage loader: 2048 16B-chunks per stage (A:1024, B:1024), 8 per thread
#define LOAD_STAGE(kt, s)                                                      \
    do {                                                                       \
        const uint32_t sa_ = sb + (s) * 2 * STG_BYTES;                         \
        const uint32_t sb_ = sa_ + STG_BYTES;                                  \
        _Pragma("unroll")                                                      \
        for (int u = 0; u < 4; ++u) {                                          \
            const int id  = tid + u * 256;                                     \
            const int row = id >> 3, c = id & 7;                               \
            const uint32_t off = row * 144 + c * 16;                           \
            cp16(sa_ + off, Ag + (size_t)(m0 + row) * 512 + (kt) * 64 + c * 8);\
            cp16(sb_ + off, Bg + (size_t)(n0 + row) * 512 + (kt) * 64 + c * 8);\
        }                                                                      \
        CP_COMMIT();                                                           \
    } while (0)

    LOAD_STAGE(0, 0);
    LOAD_STAGE(1, 1);

    for (int kt = 0; kt < 8; ++kt) {
        if (kt == 7)
            asm volatile("cp.async.wait_group 0;" ::: "memory");
        else
            asm volatile("cp.async.wait_group 1;" ::: "memory");
        __syncthreads();

        if (kt + 2 < 8) LOAD_STAGE(kt + 2, (kt + 2) % 3);

        const uint32_t sa_ = sb + (kt % 3) * 2 * STG_BYTES;
        const uint32_t sb_ = sa_ + STG_BYTES;

#pragma unroll
        for (int ks = 0; ks < 4; ++ks) {
            const int col = ks * 16 + ((lane >> 4) << 3);
            uint32_t af[4][4], bf[2][4];
#pragma unroll
            for (int mt = 0; mt < 4; ++mt) {
                const int row = wy * 64 + mt * 16 + (lane & 15);
                ldsm_x4(af[mt], sa_ + row * 144 + col * 2);
            }
#pragma unroll
            for (int np = 0; np < 2; ++np) {
                const int row =
                    wx * 32 + np * 16 + (lane & 7) + ((lane >> 3) & 1) * 8;
                ldsm_x4(bf[np], sb_ + row * 144 + col * 2);
            }
#pragma unroll
            for (int mt = 0; mt < 4; ++mt)
#pragma unroll
                for (int nt = 0; nt < 4; ++nt)
                    mma_f16(acc[mt * 4 + nt], af[mt],
                            bf[nt >> 1][nt & 1], bf[nt >> 1][(nt & 1) + 2]);
        }
    }
#undef LOAD_STAGE

    // epilogue
#pragma unroll
    for (int mt = 0; mt < 4; ++mt) {
#pragma unroll
        for (int nt = 0; nt < 4; ++nt) {
            const int m = m0 + wy * 64 + mt * 16 + (lane >> 2);
            const int n = n0 + wx * 32 + nt * 8 + ((lane & 3) << 1);
            const float* a = acc[mt * 4 + nt];
            if (MODE == 0) {
                const int sidx = n >> 9;
                const int h    = (n >> 6) & 7;
                const int d    = n & 63;
                float* dst = (sidx == 0) ? g_q : ((sidx == 1) ? g_k : g_v);
                const int win = m >> 7;
                const size_t b0i =
                    (((size_t)(win * HEADS + h)) * WIN + (m & 127)) * HD + d;
                const size_t b1i =
                    (((size_t)(win * HEADS + h)) * WIN + ((m + 8) & 127)) * HD + d;
                *(float2*)&dst[b0i] = make_float2(a[0], a[1]);
                *(float2*)&dst[b1i] = make_float2(a[2], a[3]);
            } else {
                const float2 bv = *(const float2*)&bias[n];
                *(float2*)&C[(size_t)m * 512 + n] =
                    make_float2(a[0] + bv.x, a[1] + bv.y);
                *(float2*)&C[(size_t)(m + 8) * 512 + n] =
                    make_float2(a[2] + bv.x, a[3] + bv.y);
            }
        }
    }
}

// ---------------------------------------------------------------------------
// Attention (fp32, known-good from R1): one CTA per (window, head).
// Writes fp16 g_oh directly.
// ---------------------------------------------------------------------------
#define QT_STRIDE 129
#define SS_STRIDE 132
#define ATTN_SMEM ((64 * QT_STRIDE * 2 + 128 * 64 + 128 * SS_STRIDE) * 4)

__global__ void __launch_bounds__(256)
attn128()
{
    extern __shared__ float sm[];
    float* Qt = sm;                          // [64][129] (Qt[d][t])
    float* Kt = Qt + 64 * QT_STRIDE;         // [64][129]
    float* Vs = Kt + 64 * QT_STRIDE;         // [128][64] row-major
    float* Ss = Vs + 128 * 64;               // [128][132]

    const int bh  = blockIdx.x;
    const int tid = threadIdx.x;
    const float* qg = g_q + (size_t)bh * (WIN * HD);
    const float* kg = g_k + (size_t)bh * (WIN * HD);
    const float* vg = g_v + (size_t)bh * (WIN * HD);

    for (int i = tid; i < WIN * HD; i += 256) {
        const int t = i >> 6, d = i & 63;
        Qt[d * QT_STRIDE + t] = qg[i];
        Kt[d * QT_STRIDE + t] = kg[i];
        Vs[i] = vg[i];
    }
    __syncthreads();

    const int tx = tid & 15, ty = tid >> 4;

    float acc[8][8];
#pragma unroll
    for (int i = 0; i < 8; ++i)
#pragma unroll
        for (int j = 0; j < 8; ++j) acc[i][j] = 0.0f;

#pragma unroll 4
    for (int kk = 0; kk < 64; ++kk) {
        float a[8], b[8];
#pragma unroll
        for (int i = 0; i < 4; ++i) {
            a[i]     = Qt[kk * QT_STRIDE + ty * 4 + i];
            a[4 + i] = Qt[kk * QT_STRIDE + 64 + ty * 4 + i];
            b[i]     = Kt[kk * QT_STRIDE + tx * 4 + i];
            b[4 + i] = Kt[kk * QT_STRIDE + 64 + tx * 4 + i];
        }
#pragma unroll
        for (int i = 0; i < 8; ++i)
#pragma unroll
            for (int j = 0; j < 8; ++j)
                acc[i][j] += a[i] * b[j];
    }

#pragma unroll
    for (int ii = 0; ii < 8; ++ii) {
        const int r = ((ii >> 2) * 64) + ty * 4 + (ii & 3);
#pragma unroll
        for (int jj = 0; jj < 8; ++jj) {
            const int c = ((jj >> 2) * 64) + tx * 4 + (jj & 3);
            Ss[r * SS_STRIDE + c] = (c <= r) ? acc[ii][jj] * 0.125f : -1e30f;
        }
    }
    __syncthreads();

    {
        const int row = tid >> 1, half = tid & 1;
        float* srow = Ss + row * SS_STRIDE + half * 64;
        float m = -1e30f;
#pragma unroll 8
        for (int j = 0; j < 64; ++j) m = fmaxf(m, srow[j]);
        m = fmaxf(m, __shfl_xor_sync(0xffffffffu, m, 1));
        float s = 0.0f;
#pragma unroll 8
        for (int j = 0; j < 64; ++j) {
            const float e = __expf(srow[j] - m);
            srow[j] = e;
            s += e;
        }
        s += __shfl_xor_sync(0xffffffffu, s, 1);
        const float inv = 1.0f / s;
#pragma unroll 8
        for (int j = 0; j < 64; ++j) srow[j] *= inv;
    }
    __syncthreads();

    float o[8][4];
#pragma unroll
    for (int i = 0; i < 8; ++i)
#pragma unroll
        for (int j = 0; j < 4; ++j) o[i][j] = 0.0f;

#pragma unroll 2
    for (int kk = 0; kk < 128; ++kk) {
        const float4 bv = *(const float4*)&Vs[kk * 64 + tx * 4];
        const float b4[4] = {bv.x, bv.y, bv.z, bv.w};
        float a[8];
#pragma unroll
        for (int i = 0; i < 4; ++i) {
            a[i]     = Ss[(ty * 4 + i) * SS_STRIDE + kk];
            a[4 + i] = Ss[(64 + ty * 4 + i) * SS_STRIDE + kk];
        }
#pragma unroll
        for (int i = 0; i < 8; ++i)
#pragma unroll
            for (int j = 0; j < 4; ++j)
                o[i][j] += a[i] * b4[j];
    }

    const int win = bh >> 3, h = bh & 7;
#pragma unroll
    for (int ii = 0; ii < 8; ++ii) {
        const int r = ((ii >> 2) * 64) + ty * 4 + (ii & 3);
        __half2 h0 = __floats2half2_rn(o[ii][0], o[ii][1]);
        __half2 h1 = __floats2half2_rn(o[ii][2], o[ii][3]);
        uint2 packed = make_uint2(*(uint32_t*)&h0, *(uint32_t*)&h1);
        *(uint2*)&g_oh[((size_t)(win * WIN + r) * DIMC) + h * HD + tx * 4] =
            packed;
    }
}

// ---------------------------------------------------------------------------
extern "C" void kernel_launch(void* const* d_in, const int* in_sizes, int n_in,
                              void* d_out, int out_size)
{
    const float* x      = (const float*)d_in[0];  // [16,4096,512]
    const float* w_qkv  = (const float*)d_in[1];  // [1536,512]
    const float* w_proj = (const float*)d_in[2];  // [512,512]
    const float* b_proj = (const float*)d_in[3];  // [512]
    float* out = (float*)d_out;                   // [16,4096,512]

    cudaFuncSetAttribute(hgemm<0>, cudaFuncAttributeMaxDynamicSharedMemorySize,
                         GEMM_SMEM);
    cudaFuncSetAttribute(hgemm<1>, cudaFuncAttributeMaxDynamicSharedMemorySize,
                         GEMM_SMEM);
    cudaFuncSetAttribute(attn128, cudaFuncAttributeMaxDynamicSharedMemorySize,
                         ATTN_SMEM);

    // 0) fp32 -> fp16 conversions
    {
        __half* p_hx = nullptr;  __half* p_wq = nullptr;  __half* p_wp = nullptr;
        cudaGetSymbolAddress((void**)&p_hx, hx);
        cudaGetSymbolAddress((void**)&p_wq, hwqkv);
        cudaGetSymbolAddress((void**)&p_wp, hwproj);
        cvt_f2h<<<(NTOK * DIMC / 4 + 255) / 256, 256>>>(x, p_hx, NTOK * DIMC / 4);
        cvt_f2h<<<(3 * DIMC * DIMC / 4 + 255) / 256, 256>>>(w_qkv, p_wq,
                                                            3 * DIMC * DIMC / 4);
        cvt_f2h<<<(DIMC * DIMC / 4 + 255) / 256, 256>>>(w_proj, p_wp,
                                                        DIMC * DIMC / 4);
    }

    // 1) fused QKV projection (fp16 HMMA) -> fp32 g_q/g_k/g_v
    dim3 g1(1536 / 128, NTOK / 128);
    hgemm<0><<<g1, 256, GEMM_SMEM>>>(nullptr, nullptr);

    // 2) per-(window,head) attention (fp32) -> fp16 g_oh
    attn128<<<BH, 256, ATTN_SMEM>>>();

    // 3) output projection + bias (fp16 HMMA) -> fp32 d_out
    dim3 g2(512 / 128, NTOK / 128);
    hgemm<1><<<g2, 256, GEMM_SMEM>>>(out, b_proj);
}

// round 4
// speedup vs baseline: 5.0901x; 1.8256x over previous
#include <cuda_runtime.h>
#include <cuda_fp16.h>
#include <cstdint>

// Problem constants
#define DIMC   512
#define HEADS  8
#define WIN    128
#define HD     64
#define NTOK   65536          // 16*4096
#define NWIN   512            // NTOK/WIN
#define BH     (NWIN*HEADS)   // 4096

// Scratch (device globals)
__device__ __half hx[(size_t)NTOK * DIMC];        // fp16 copy of x
__device__ __half hwqkv[(size_t)3 * DIMC * DIMC]; // fp16 w_qkv
__device__ __half hwproj[(size_t)DIMC * DIMC];    // fp16 w_proj
__device__ __half g_qh[(size_t)BH * WIN * HD];    // fp16 q [win,h,t,d]
__device__ __half g_kh[(size_t)BH * WIN * HD];
__device__ __half g_vh[(size_t)BH * WIN * HD];
__device__ __half g_oh[(size_t)NTOK * DIMC];      // fp16 attention output

// ---------------------------------------------------------------------------
// helpers
// ---------------------------------------------------------------------------
__device__ __forceinline__ uint32_t s2u(const void* p) {
    uint32_t a;
    asm("{ .reg .u64 t; cvta.to.shared.u64 t, %1; cvt.u32.u64 %0, t; }"
        : "=r"(a) : "l"(p));
    return a;
}

__device__ __forceinline__ void cp16(uint32_t dst, const void* src) {
    asm volatile("cp.async.cg.shared.global [%0], [%1], 16;" :: "r"(dst), "l"(src));
}
#define CP_COMMIT() asm volatile("cp.async.commit_group;" ::: "memory")

__device__ __forceinline__ void ldsm_x4(uint32_t* r, uint32_t a) {
    asm volatile("ldmatrix.sync.aligned.m8n8.x4.shared.b16 {%0,%1,%2,%3}, [%4];"
        : "=r"(r[0]), "=r"(r[1]), "=r"(r[2]), "=r"(r[3]) : "r"(a));
}

__device__ __forceinline__ void ldsm_x4t(uint32_t* r, uint32_t a) {
    asm volatile("ldmatrix.sync.aligned.m8n8.x4.trans.shared.b16 {%0,%1,%2,%3}, [%4];"
        : "=r"(r[0]), "=r"(r[1]), "=r"(r[2]), "=r"(r[3]) : "r"(a));
}

__device__ __forceinline__ void mma_f16(float* d, const uint32_t* a,
                                        const uint32_t b0, const uint32_t b1) {
    asm volatile(
        "mma.sync.aligned.m16n8k16.row.col.f32.f16.f16.f32 "
        "{%0,%1,%2,%3}, {%4,%5,%6,%7}, {%8,%9}, {%0,%1,%2,%3};"
        : "+f"(d[0]), "+f"(d[1]), "+f"(d[2]), "+f"(d[3])
        : "r"(a[0]), "r"(a[1]), "r"(a[2]), "r"(a[3]), "r"(b0), "r"(b1));
}

__device__ __forceinline__ uint32_t packh2(float x, float y) {
    __half2 h = __floats2half2_rn(x, y);
    return *(uint32_t*)&h;
}

// ---------------------------------------------------------------------------
// fp32 -> fp16 conversion
// ---------------------------------------------------------------------------
__global__ void cvt_f2h(const float* __restrict__ src, __half* __restrict__ dst,
                        int n4)
{
    int i = blockIdx.x * blockDim.x + threadIdx.x;
    if (i < n4) {
        float4 v = ((const float4*)src)[i];
        ((__half2*)dst)[2 * i]     = __floats2half2_rn(v.x, v.y);
        ((__half2*)dst)[2 * i + 1] = __floats2half2_rn(v.z, v.w);
    }
}

// ---------------------------------------------------------------------------
// fp16 HMMA GEMM: C[m,n] = sum_k A[m,k]*B[n,k], K=512.
// BM=BN=128, BK=64, 3-stage cp.async, 512 threads / 16 warps, warp tile 32x32.
// MODE 0: A=hx, B=hwqkv -> fp16 scatter into g_qh/g_kh/g_vh [win,h,t,d]
// MODE 1: A=g_oh, B=hwproj, +bias -> fp32 C
// ---------------------------------------------------------------------------
#define STG_BYTES (128 * 144)                // 18432 per matrix tile
#define GEMM_SMEM (3 * 2 * STG_BYTES)        // 110592

template<int MODE>
__global__ void __launch_bounds__(512, 1)
hgemm(float* __restrict__ C, const float* __restrict__ bias)
{
    extern __shared__ __align__(128) char smem[];
    const __half* Ag = (MODE == 0) ? hx : g_oh;
    const __half* Bg = (MODE == 0) ? hwqkv : hwproj;

    const uint32_t sb = s2u(smem);
    const int tid  = threadIdx.x;
    const int m0   = blockIdx.y * 128;
    const int n0   = blockIdx.x * 128;
    const int warp = tid >> 5, lane = tid & 31;
    const int wy   = warp >> 2, wx = warp & 3;   // warp tile: (wy*32, wx*32)

    float acc[8][4];                             // [mt*4+nt]
#pragma unroll
    for (int i = 0; i < 8; ++i)
#pragma unroll
        for (int j = 0; j < 4; ++j) acc[i][j] = 0.0f;

    // stage loader: 1024 16B-chunks per matrix; 512 threads -> 2 A + 2 B each
#define LOAD_STAGE(kt, s)                                                      \
    do {                                                                       \
        const uint32_t sa_ = sb + (s) * 2 * STG_BYTES;                         \
        const uint32_t sb2_ = sa_ + STG_BYTES;                                 \
        _Pragma("unroll")                                                      \
        for (int u = 0; u < 2; ++u) {                                          \
            const int id  = tid + u * 512;                                     \
            const int row = id >> 3, c = id & 7;                               \
            const uint32_t off = row * 144 + c * 16;                           \
            cp16(sa_ + off, Ag + (size_t)(m0 + row) * 512 + (kt) * 64 + c * 8);\
            cp16(sb2_ + off, Bg + (size_t)(n0 + row) * 512 + (kt) * 64 + c * 8);\
        }                                                                      \
        CP_COMMIT();                                                           \
    } while (0)

    LOAD_STAGE(0, 0);
    LOAD_STAGE(1, 1);

    for (int kt = 0; kt < 8; ++kt) {
        if (kt == 7)
            asm volatile("cp.async.wait_group 0;" ::: "memory");
        else
            asm volatile("cp.async.wait_group 1;" ::: "memory");
        __syncthreads();

        if (kt + 2 < 8) LOAD_STAGE(kt + 2, (kt + 2) % 3);

        const uint32_t sa_  = sb + (kt % 3) * 2 * STG_BYTES;
        const uint32_t sb2_ = sa_ + STG_BYTES;

#pragma unroll
        for (int ks = 0; ks < 4; ++ks) {
            const int col = ks * 16 + ((lane >> 4) << 3);
            uint32_t af[2][4], bf[2][4];
#pragma unroll
            for (int mt = 0; mt < 2; ++mt) {
                const int row = wy * 32 + mt * 16 + (lane & 15);
                ldsm_x4(af[mt], sa_ + row * 144 + col * 2);
            }
#pragma unroll
            for (int np = 0; np < 2; ++np) {
                const int row =
                    wx * 32 + np * 16 + (lane & 7) + ((lane >> 3) & 1) * 8;
                ldsm_x4(bf[np], sb2_ + row * 144 + col * 2);
            }
#pragma unroll
            for (int mt = 0; mt < 2; ++mt)
#pragma unroll
                for (int nt = 0; nt < 4; ++nt)
                    mma_f16(acc[mt * 4 + nt], af[mt],
                            bf[nt >> 1][nt & 1], bf[nt >> 1][(nt & 1) + 2]);
        }
    }
#undef LOAD_STAGE

    // epilogue
#pragma unroll
    for (int mt = 0; mt < 2; ++mt) {
#pragma unroll
        for (int nt = 0; nt < 4; ++nt) {
            const int m = m0 + wy * 32 + mt * 16 + (lane >> 2);
            const int n = n0 + wx * 32 + nt * 8 + ((lane & 3) << 1);
            const float* a = acc[mt * 4 + nt];
            if (MODE == 0) {
                const int sidx = n >> 9;
                const int h    = (n >> 6) & 7;
                const int d    = n & 63;
                __half* dst = (sidx == 0) ? g_qh : ((sidx == 1) ? g_kh : g_vh);
                const int win = m >> 7;
                const size_t b0i =
                    (((size_t)(win * HEADS + h)) * WIN + (m & 127)) * HD + d;
                const size_t b1i = b0i + 8 * HD;
                *(uint32_t*)&dst[b0i] = packh2(a[0], a[1]);
                *(uint32_t*)&dst[b1i] = packh2(a[2], a[3]);
            } else {
                const float2 bv = *(const float2*)&bias[n];
                *(float2*)&C[(size_t)m * 512 + n] =
                    make_float2(a[0] + bv.x, a[1] + bv.y);
                *(float2*)&C[(size_t)(m + 8) * 512 + n] =
                    make_float2(a[2] + bv.x, a[3] + bv.y);
            }
        }
    }
}

// ---------------------------------------------------------------------------
// HMMA attention: one CTA per (window, head), 256 threads / 8 warps.
// Warp w owns query rows [w*16, w*16+16). S = Q K^T (fp32 accum), register
// softmax (rows fully warp-owned), P fragment reused directly for P*V.
// ---------------------------------------------------------------------------
#define APAD 144                             // bytes per smem row (72 halfs)
#define ATILE (128 * APAD)                   // 18432
#define ATTN_SMEM (3 * ATILE)                // 55296

__global__ void __launch_bounds__(256, 1)
attn_tc()
{
    extern __shared__ __align__(128) char smem[];
    const uint32_t sQ = s2u(smem);
    const uint32_t sK = sQ + ATILE;
    const uint32_t sV = sK + ATILE;

    const int bh   = blockIdx.x;
    const int tid  = threadIdx.x;
    const int warp = tid >> 5, lane = tid & 31;

    const __half* qg = g_qh + (size_t)bh * (WIN * HD);
    const __half* kg = g_kh + (size_t)bh * (WIN * HD);
    const __half* vg = g_vh + (size_t)bh * (WIN * HD);

    // load Q,K,V tiles (each 128 rows x 64 halfs = 1024 16B chunks)
#pragma unroll
    for (int u = 0; u < 4; ++u) {
        const int id  = tid + u * 256;
        const int row = id >> 3, c = id & 7;
        const uint32_t off = row * APAD + c * 16;
        cp16(sQ + off, qg + row * 64 + c * 8);
        cp16(sK + off, kg + row * 64 + c * 8);
        cp16(sV + off, vg + row * 64 + c * 8);
    }
    CP_COMMIT();
    asm volatile("cp.async.wait_group 0;" ::: "memory");
    __syncthreads();

    // ---- S = Q K^T : per warp 16 x 128, fp32 accum ----
    float sacc[16][4];
#pragma unroll
    for (int i = 0; i < 16; ++i)
#pragma unroll
        for (int j = 0; j < 4; ++j) sacc[i][j] = 0.0f;

#pragma unroll
    for (int ks = 0; ks < 4; ++ks) {
        const int col = ks * 16 + ((lane >> 4) << 3);
        uint32_t af[4];
        {
            const int row = warp * 16 + (lane & 15);
            ldsm_x4(af, sQ + row * APAD + col * 2);
        }
#pragma unroll
        for (int np = 0; np < 8; ++np) {
            uint32_t bf[4];
            const int row = np * 16 + (lane & 7) + ((lane >> 3) & 1) * 8;
            ldsm_x4(bf, sK + row * APAD + col * 2);
            mma_f16(sacc[np * 2 + 0], af, bf[0], bf[2]);
            mma_f16(sacc[np * 2 + 1], af, bf[1], bf[3]);
        }
    }

    // ---- causal mask + softmax in registers ----
    const int rlo = warp * 16 + (lane >> 2);   // low query row
    const int rhi = rlo + 8;
    float mx0 = -1e30f, mx1 = -1e30f;
#pragma unroll
    for (int nt = 0; nt < 16; ++nt) {
        const int cb = nt * 8 + ((lane & 3) << 1);
        float s0 = sacc[nt][0] * 0.125f;
        float s1 = sacc[nt][1] * 0.125f;
        float s2 = sacc[nt][2] * 0.125f;
        float s3 = sacc[nt][3] * 0.125f;
        if (cb     > rlo) s0 = -1e30f;
        if (cb + 1 > rlo) s1 = -1e30f;
        if (cb     > rhi) s2 = -1e30f;
        if (cb + 1 > rhi) s3 = -1e30f;
        sacc[nt][0] = s0; sacc[nt][1] = s1;
        sacc[nt][2] = s2; sacc[nt][3] = s3;
        mx0 = fmaxf(mx0, fmaxf(s0, s1));
        mx1 = fmaxf(mx1, fmaxf(s2, s3));
    }
    mx0 = fmaxf(mx0, __shfl_xor_sync(0xffffffffu, mx0, 1));
    mx0 = fmaxf(mx0, __shfl_xor_sync(0xffffffffu, mx0, 2));
    mx1 = fmaxf(mx1, __shfl_xor_sync(0xffffffffu, mx1, 1));
    mx1 = fmaxf(mx1, __shfl_xor_sync(0xffffffffu, mx1, 2));

    float sum0 = 0.0f, sum1 = 0.0f;
#pragma unroll
    for (int nt = 0; nt < 16; ++nt) {
        float e0 = __expf(sacc[nt][0] - mx0);
        float e1 = __expf(sacc[nt][1] - mx0);
        float e2 = __expf(sacc[nt][2] - mx1);
        float e3 = __expf(sacc[nt][3] - mx1);
        sacc[nt][0] = e0; sacc[nt][1] = e1;
        sacc[nt][2] = e2; sacc[nt][3] = e3;
        sum0 += e0 + e1;
        sum1 += e2 + e3;
    }
    sum0 += __shfl_xor_sync(0xffffffffu, sum0, 1);
    sum0 += __shfl_xor_sync(0xffffffffu, sum0, 2);
    sum1 += __shfl_xor_sync(0xffffffffu, sum1, 1);
    sum1 += __shfl_xor_sync(0xffffffffu, sum1, 2);
    const float inv0 = 1.0f / sum0;
    const float inv1 = 1.0f / sum1;

    // ---- O = P V : per warp 16 x 64 ----
    float oacc[8][4];
#pragma unroll
    for (int i = 0; i < 8; ++i)
#pragma unroll
        for (int j = 0; j < 4; ++j) oacc[i][j] = 0.0f;

#pragma unroll
    for (int kt = 0; kt < 8; ++kt) {
        // P A-fragment from S fragment (layout identity)
        uint32_t ap[4];
        ap[0] = packh2(sacc[2 * kt][0] * inv0,     sacc[2 * kt][1] * inv0);
        ap[1] = packh2(sacc[2 * kt][2] * inv1,     sacc[2 * kt][3] * inv1);
        ap[2] = packh2(sacc[2 * kt + 1][0] * inv0, sacc[2 * kt + 1][1] * inv0);
        ap[3] = packh2(sacc[2 * kt + 1][2] * inv1, sacc[2 * kt + 1][3] * inv1);

#pragma unroll
        for (int nb = 0; nb < 4; ++nb) {
            uint32_t bv[4];
            const int row = kt * 16 + (lane & 15);
            const int col = nb * 16 + ((lane >> 4) << 3);
            ldsm_x4t(bv, sV + row * APAD + col * 2);
            mma_f16(oacc[nb * 2 + 0], ap, bv[0], bv[1]);
            mma_f16(oacc[nb * 2 + 1], ap, bv[2], bv[3]);
        }
    }

    // ---- write O to g_oh [token][C] fp16 ----
    const int win = bh >> 3, h = bh & 7;
    const size_t row_lo = (size_t)(win * WIN + warp * 16 + (lane >> 2)) * DIMC
                          + h * HD + ((lane & 3) << 1);
#pragma unroll
    for (int nt = 0; nt < 8; ++nt) {
        *(uint32_t*)&g_oh[row_lo + nt * 8]              = packh2(oacc[nt][0], oacc[nt][1]);
        *(uint32_t*)&g_oh[row_lo + 8 * DIMC + nt * 8]   = packh2(oacc[nt][2], oacc[nt][3]);
    }
}

// ---------------------------------------------------------------------------
extern "C" void kernel_launch(void* const* d_in, const int* in_sizes, int n_in,
                              void* d_out, int out_size)
{
    const float* x      = (const float*)d_in[0];  // [16,4096,512]
    const float* w_qkv  = (const float*)d_in[1];  // [1536,512]
    const float* w_proj = (const float*)d_in[2];  // [512,512]
    const float* b_proj = (const float*)d_in[3];  // [512]
    float* out = (float*)d_out;                   // [16,4096,512]

    cudaFuncSetAttribute(hgemm<0>, cudaFuncAttributeMaxDynamicSharedMemorySize,
                         GEMM_SMEM);
    cudaFuncSetAttribute(hgemm<1>, cudaFuncAttributeMaxDynamicSharedMemorySize,
                         GEMM_SMEM);
    cudaFuncSetAttribute(attn_tc, cudaFuncAttributeMaxDynamicSharedMemorySize,
                         ATTN_SMEM);

    // 0) fp32 -> fp16 conversions
    {
        __half* p_hx = nullptr;  __half* p_wq = nullptr;  __half* p_wp = nullptr;
        cudaGetSymbolAddress((void**)&p_hx, hx);
        cudaGetSymbolAddress((void**)&p_wq, hwqkv);
        cudaGetSymbolAddress((void**)&p_wp, hwproj);
        cvt_f2h<<<(NTOK * DIMC / 4 + 255) / 256, 256>>>(x, p_hx, NTOK * DIMC / 4);
        cvt_f2h<<<(3 * DIMC * DIMC / 4 + 255) / 256, 256>>>(w_qkv, p_wq,
                                                            3 * DIMC * DIMC / 4);
        cvt_f2h<<<(DIMC * DIMC / 4 + 255) / 256, 256>>>(w_proj, p_wp,
                                                        DIMC * DIMC / 4);
    }

    // 1) fused QKV projection -> fp16 g_qh/g_kh/g_vh
    dim3 g1(1536 / 128, NTOK / 128);
    hgemm<0><<<g1, 512, GEMM_SMEM>>>(nullptr, nullptr);

    // 2) HMMA attention -> fp16 g_oh
    attn_tc<<<BH, 256, ATTN_SMEM>>>();

    // 3) output projection + bias -> fp32 d_out
    dim3 g2(512 / 128, NTOK / 128);
    hgemm<1><<<g2, 512, GEMM_SMEM>>>(out, b_proj);
}

// round 5
// speedup vs baseline: 5.2993x; 1.0411x over previous
#include <cuda_runtime.h>
#include <cuda_fp16.h>
#include <cstdint>

// Problem constants
#define DIMC   512
#define HEADS  8
#define WIN    128
#define HD     64
#define NTOK   65536          // 16*4096
#define NWIN   512            // NTOK/WIN
#define BH     (NWIN*HEADS)   // 4096

// Scratch (device globals)
__device__ __half hx[(size_t)NTOK * DIMC];        // fp16 copy of x
__device__ __half hwqkv[(size_t)3 * DIMC * DIMC]; // fp16 w_qkv
__device__ __half hwproj[(size_t)DIMC * DIMC];    // fp16 w_proj
__device__ __half g_qh[(size_t)BH * WIN * HD];    // fp16 q [win,h,t,d]
__device__ __half g_kh[(size_t)BH * WIN * HD];
__device__ __half g_vh[(size_t)BH * WIN * HD];
__device__ __half g_oh[(size_t)NTOK * DIMC];      // fp16 attention output

// ---------------------------------------------------------------------------
// helpers
// ---------------------------------------------------------------------------
__device__ __forceinline__ uint32_t s2u(const void* p) {
    uint32_t a;
    asm("{ .reg .u64 t; cvta.to.shared.u64 t, %1; cvt.u32.u64 %0, t; }"
        : "=r"(a) : "l"(p));
    return a;
}

__device__ __forceinline__ void cp16(uint32_t dst, const void* src) {
    asm volatile("cp.async.cg.shared.global [%0], [%1], 16;" :: "r"(dst), "l"(src));
}
#define CP_COMMIT() asm volatile("cp.async.commit_group;" ::: "memory")

__device__ __forceinline__ void ldsm_x4(uint32_t* r, uint32_t a) {
    asm volatile("ldmatrix.sync.aligned.m8n8.x4.shared.b16 {%0,%1,%2,%3}, [%4];"
        : "=r"(r[0]), "=r"(r[1]), "=r"(r[2]), "=r"(r[3]) : "r"(a));
}

__device__ __forceinline__ void ldsm_x4t(uint32_t* r, uint32_t a) {
    asm volatile("ldmatrix.sync.aligned.m8n8.x4.trans.shared.b16 {%0,%1,%2,%3}, [%4];"
        : "=r"(r[0]), "=r"(r[1]), "=r"(r[2]), "=r"(r[3]) : "r"(a));
}

__device__ __forceinline__ void mma_f16(float* d, const uint32_t* a,
                                        const uint32_t b0, const uint32_t b1) {
    asm volatile(
        "mma.sync.aligned.m16n8k16.row.col.f32.f16.f16.f32 "
        "{%0,%1,%2,%3}, {%4,%5,%6,%7}, {%8,%9}, {%0,%1,%2,%3};"
        : "+f"(d[0]), "+f"(d[1]), "+f"(d[2]), "+f"(d[3])
        : "r"(a[0]), "r"(a[1]), "r"(a[2]), "r"(a[3]), "r"(b0), "r"(b1));
}

__device__ __forceinline__ uint32_t packh2(float x, float y) {
    __half2 h = __floats2half2_rn(x, y);
    return *(uint32_t*)&h;
}

// ---------------------------------------------------------------------------
// fp32 -> fp16 conversion
// ---------------------------------------------------------------------------
__global__ void cvt_f2h(const float* __restrict__ src, __half* __restrict__ dst,
                        int n4)
{
    int i = blockIdx.x * blockDim.x + threadIdx.x;
    if (i < n4) {
        float4 v = ((const float4*)src)[i];
        ((__half2*)dst)[2 * i]     = __floats2half2_rn(v.x, v.y);
        ((__half2*)dst)[2 * i + 1] = __floats2half2_rn(v.z, v.w);
    }
}

// ---------------------------------------------------------------------------
// fp16 HMMA GEMM: C[m,n] = sum_k A[m,k]*B[n,k], K=512.
// Block tile 128x256, BK=64, 3-stage cp.async, 512 threads / 16 warps,
// warp tile 32x64 (2 A-ldsm + 4 B-ldsm -> 16 MMAs per k16).
// MODE 0: A=hx, B=hwqkv -> fp16 scatter into g_qh/g_kh/g_vh [win,h,t,d]
// MODE 1: A=g_oh, B=hwproj, +bias -> fp32 C
// ---------------------------------------------------------------------------
#define A_STG 18432                          // 128 rows * 144 B
#define B_STG 36864                          // 256 rows * 144 B
#define STG   (A_STG + B_STG)                // 55296
#define GEMM_SMEM (3 * STG)                  // 165888

template<int MODE>
__global__ void __launch_bounds__(512, 1)
hgemm(float* __restrict__ C, const float* __restrict__ bias)
{
    extern __shared__ __align__(128) char smem[];
    const __half* Ag = (MODE == 0) ? hx : g_oh;
    const __half* Bg = (MODE == 0) ? hwqkv : hwproj;

    const uint32_t sb = s2u(smem);
    const int tid  = threadIdx.x;
    const int m0   = blockIdx.y * 128;
    const int n0   = blockIdx.x * 256;
    const int warp = tid >> 5, lane = tid & 31;
    const int wy   = warp >> 2, wx = warp & 3;   // warp tile: (wy*32, wx*64)

    float acc[16][4];                            // [mt*8+nt]
#pragma unroll
    for (int i = 0; i < 16; ++i)
#pragma unroll
        for (int j = 0; j < 4; ++j) acc[i][j] = 0.0f;

    const int lrow = tid >> 3;                   // 0..63
    const int lc   = tid & 7;

#define LOAD_STAGE(kt, s)                                                      \
    do {                                                                       \
        const uint32_t sa_  = sb + (s) * STG;                                  \
        const uint32_t sb2_ = sa_ + A_STG;                                     \
        _Pragma("unroll")                                                      \
        for (int u = 0; u < 2; ++u) {                                          \
            const int row = lrow + u * 64;                                     \
            cp16(sa_ + row * 144 + lc * 16,                                    \
                 Ag + (size_t)(m0 + row) * 512 + (kt) * 64 + lc * 8);          \
        }                                                                      \
        _Pragma("unroll")                                                      \
        for (int u = 0; u < 4; ++u) {                                          \
            const int row = lrow + u * 64;                                     \
            cp16(sb2_ + row * 144 + lc * 16,                                   \
                 Bg + (size_t)(n0 + row) * 512 + (kt) * 64 + lc * 8);          \
        }                                                                      \
        CP_COMMIT();                                                           \
    } while (0)

    LOAD_STAGE(0, 0);
    LOAD_STAGE(1, 1);

    for (int kt = 0; kt < 8; ++kt) {
        if (kt == 7)
            asm volatile("cp.async.wait_group 0;" ::: "memory");
        else
            asm volatile("cp.async.wait_group 1;" ::: "memory");
        __syncthreads();

        if (kt + 2 < 8) LOAD_STAGE(kt + 2, (kt + 2) % 3);

        const uint32_t sa_  = sb + (kt % 3) * STG;
        const uint32_t sb2_ = sa_ + A_STG;

#pragma unroll
        for (int ks = 0; ks < 4; ++ks) {
            const int col = ks * 16 + ((lane >> 4) << 3);
            uint32_t af[2][4], bf[4][4];
#pragma unroll
            for (int mt = 0; mt < 2; ++mt) {
                const int row = wy * 32 + mt * 16 + (lane & 15);
                ldsm_x4(af[mt], sa_ + row * 144 + col * 2);
            }
#pragma unroll
            for (int np = 0; np < 4; ++np) {
                const int row =
                    wx * 64 + np * 16 + (lane & 7) + ((lane >> 3) & 1) * 8;
                ldsm_x4(bf[np], sb2_ + row * 144 + col * 2);
            }
#pragma unroll
            for (int mt = 0; mt < 2; ++mt)
#pragma unroll
                for (int nt = 0; nt < 8; ++nt)
                    mma_f16(acc[mt * 8 + nt], af[mt],
                            bf[nt >> 1][nt & 1], bf[nt >> 1][(nt & 1) + 2]);
        }
    }
#undef LOAD_STAGE

    // epilogue
#pragma unroll
    for (int mt = 0; mt < 2; ++mt) {
#pragma unroll
        for (int nt = 0; nt < 8; ++nt) {
            const int m = m0 + wy * 32 + mt * 16 + (lane >> 2);
            const int n = n0 + wx * 64 + nt * 8 + ((lane & 3) << 1);
            const float* a = acc[mt * 8 + nt];
            if (MODE == 0) {
                const int sidx = n >> 9;
                const int h    = (n >> 6) & 7;
                const int d    = n & 63;
                __half* dst = (sidx == 0) ? g_qh : ((sidx == 1) ? g_kh : g_vh);
                const int win = m >> 7;
                const size_t b0i =
                    (((size_t)(win * HEADS + h)) * WIN + (m & 127)) * HD + d;
                const size_t b1i = b0i + 8 * HD;
                *(uint32_t*)&dst[b0i] = packh2(a[0], a[1]);
                *(uint32_t*)&dst[b1i] = packh2(a[2], a[3]);
            } else {
                const float2 bv = *(const float2*)&bias[n];
                *(float2*)&C[(size_t)m * 512 + n] =
                    make_float2(a[0] + bv.x, a[1] + bv.y);
                *(float2*)&C[(size_t)(m + 8) * 512 + n] =
                    make_float2(a[2] + bv.x, a[3] + bv.y);
            }
        }
    }
}

// ---------------------------------------------------------------------------
// HMMA attention: one CTA per (window, head), 256 threads / 8 warps.
// Warp w owns query rows [w*16, w*16+16). S = Q K^T (fp32 accum), register
// softmax, P fragment reused directly for P*V.
// ---------------------------------------------------------------------------
#define APAD 144                             // bytes per smem row (72 halfs)
#define ATILE (128 * APAD)                   // 18432
#define ATTN_SMEM (3 * ATILE)                // 55296

__global__ void __launch_bounds__(256, 1)
attn_tc()
{
    extern __shared__ __align__(128) char smem[];
    const uint32_t sQ = s2u(smem);
    const uint32_t sK = sQ + ATILE;
    const uint32_t sV = sK + ATILE;

    const int bh   = blockIdx.x;
    const int tid  = threadIdx.x;
    const int warp = tid >> 5, lane = tid & 31;

    const __half* qg = g_qh + (size_t)bh * (WIN * HD);
    const __half* kg = g_kh + (size_t)bh * (WIN * HD);
    const __half* vg = g_vh + (size_t)bh * (WIN * HD);

#pragma unroll
    for (int u = 0; u < 4; ++u) {
        const int id  = tid + u * 256;
        const int row = id >> 3, c = id & 7;
        const uint32_t off = row * APAD + c * 16;
        cp16(sQ + off, qg + row * 64 + c * 8);
        cp16(sK + off, kg + row * 64 + c * 8);
        cp16(sV + off, vg + row * 64 + c * 8);
    }
    CP_COMMIT();
    asm volatile("cp.async.wait_group 0;" ::: "memory");
    __syncthreads();

    // ---- S = Q K^T : per warp 16 x 128, fp32 accum ----
    float sacc[16][4];
#pragma unroll
    for (int i = 0; i < 16; ++i)
#pragma unroll
        for (int j = 0; j < 4; ++j) sacc[i][j] = 0.0f;

#pragma unroll
    for (int ks = 0; ks < 4; ++ks) {
        const int col = ks * 16 + ((lane >> 4) << 3);
        uint32_t af[4];
        {
            const int row = warp * 16 + (lane & 15);
            ldsm_x4(af, sQ + row * APAD + col * 2);
        }
#pragma unroll
        for (int np = 0; np < 8; ++np) {
            uint32_t bf[4];
            const int row = np * 16 + (lane & 7) + ((lane >> 3) & 1) * 8;
            ldsm_x4(bf, sK + row * APAD + col * 2);
            mma_f16(sacc[np * 2 + 0], af, bf[0], bf[2]);
            mma_f16(sacc[np * 2 + 1], af, bf[1], bf[3]);
        }
    }

    // ---- causal mask + softmax in registers ----
    const int rlo = warp * 16 + (lane >> 2);
    const int rhi = rlo + 8;
    float mx0 = -1e30f, mx1 = -1e30f;
#pragma unroll
    for (int nt = 0; nt < 16; ++nt) {
        const int cb = nt * 8 + ((lane & 3) << 1);
        float s0 = sacc[nt][0] * 0.125f;
        float s1 = sacc[nt][1] * 0.125f;
        float s2 = sacc[nt][2] * 0.125f;
        float s3 = sacc[nt][3] * 0.125f;
        if (cb     > rlo) s0 = -1e30f;
        if (cb + 1 > rlo) s1 = -1e30f;
        if (cb     > rhi) s2 = -1e30f;
        if (cb + 1 > rhi) s3 = -1e30f;
        sacc[nt][0] = s0; sacc[nt][1] = s1;
        sacc[nt][2] = s2; sacc[nt][3] = s3;
        mx0 = fmaxf(mx0, fmaxf(s0, s1));
        mx1 = fmaxf(mx1, fmaxf(s2, s3));
    }
    mx0 = fmaxf(mx0, __shfl_xor_sync(0xffffffffu, mx0, 1));
    mx0 = fmaxf(mx0, __shfl_xor_sync(0xffffffffu, mx0, 2));
    mx1 = fmaxf(mx1, __shfl_xor_sync(0xffffffffu, mx1, 1));
    mx1 = fmaxf(mx1, __shfl_xor_sync(0xffffffffu, mx1, 2));

    float sum0 = 0.0f, sum1 = 0.0f;
#pragma unroll
    for (int nt = 0; nt < 16; ++nt) {
        float e0 = __expf(sacc[nt][0] - mx0);
        float e1 = __expf(sacc[nt][1] - mx0);
        float e2 = __expf(sacc[nt][2] - mx1);
        float e3 = __expf(sacc[nt][3] - mx1);
        sacc[nt][0] = e0; sacc[nt][1] = e1;
        sacc[nt][2] = e2; sacc[nt][3] = e3;
        sum0 += e0 + e1;
        sum1 += e2 + e3;
    }
    sum0 += __shfl_xor_sync(0xffffffffu, sum0, 1);
    sum0 += __shfl_xor_sync(0xffffffffu, sum0, 2);
    sum1 += __shfl_xor_sync(0xffffffffu, sum1, 1);
    sum1 += __shfl_xor_sync(0xffffffffu, sum1, 2);
    const float inv0 = 1.0f / sum0;
    const float inv1 = 1.0f / sum1;

    // ---- O = P V : per warp 16 x 64 ----
    float oacc[8][4];
#pragma unroll
    for (int i = 0; i < 8; ++i)
#pragma unroll
        for (int j = 0; j < 4; ++j) oacc[i][j] = 0.0f;

#pragma unroll
    for (int kt = 0; kt < 8; ++kt) {
        uint32_t ap[4];
        ap[0] = packh2(sacc[2 * kt][0] * inv0,     sacc[2 * kt][1] * inv0);
        ap[1] = packh2(sacc[2 * kt][2] * inv1,     sacc[2 * kt][3] * inv1);
        ap[2] = packh2(sacc[2 * kt + 1][0] * inv0, sacc[2 * kt + 1][1] * inv0);
        ap[3] = packh2(sacc[2 * kt + 1][2] * inv1, sacc[2 * kt + 1][3] * inv1);

#pragma unroll
        for (int nb = 0; nb < 4; ++nb) {
            uint32_t bv[4];
            const int row = kt * 16 + (lane & 15);
            const int col = nb * 16 + ((lane >> 4) << 3);
            ldsm_x4t(bv, sV + row * APAD + col * 2);
            mma_f16(oacc[nb * 2 + 0], ap, bv[0], bv[1]);
            mma_f16(oacc[nb * 2 + 1], ap, bv[2], bv[3]);
        }
    }

    // ---- write O to g_oh [token][C] fp16 ----
    const int win = bh >> 3, h = bh & 7;
    const size_t row_lo = (size_t)(win * WIN + warp * 16 + (lane >> 2)) * DIMC
                          + h * HD + ((lane & 3) << 1);
#pragma unroll
    for (int nt = 0; nt < 8; ++nt) {
        *(uint32_t*)&g_oh[row_lo + nt * 8]            = packh2(oacc[nt][0], oacc[nt][1]);
        *(uint32_t*)&g_oh[row_lo + 8 * DIMC + nt * 8] = packh2(oacc[nt][2], oacc[nt][3]);
    }
}

// ---------------------------------------------------------------------------
extern "C" void kernel_launch(void* const* d_in, const int* in_sizes, int n_in,
                              void* d_out, int out_size)
{
    const float* x      = (const float*)d_in[0];  // [16,4096,512]
    const float* w_qkv  = (const float*)d_in[1];  // [1536,512]
    const float* w_proj = (const float*)d_in[2];  // [512,512]
    const float* b_proj = (const float*)d_in[3];  // [512]
    float* out = (float*)d_out;                   // [16,4096,512]

    cudaFuncSetAttribute(hgemm<0>, cudaFuncAttributeMaxDynamicSharedMemorySize,
                         GEMM_SMEM);
    cudaFuncSetAttribute(hgemm<1>, cudaFuncAttributeMaxDynamicSharedMemorySize,
                         GEMM_SMEM);
    cudaFuncSetAttribute(attn_tc, cudaFuncAttributeMaxDynamicSharedMemorySize,
                         ATTN_SMEM);

    // 0) fp32 -> fp16 conversions
    {
        __half* p_hx = nullptr;  __half* p_wq = nullptr;  __half* p_wp = nullptr;
        cudaGetSymbolAddress((void**)&p_hx, hx);
        cudaGetSymbolAddress((void**)&p_wq, hwqkv);
        cudaGetSymbolAddress((void**)&p_wp, hwproj);
        cvt_f2h<<<(NTOK * DIMC / 4 + 255) / 256, 256>>>(x, p_hx, NTOK * DIMC / 4);
        cvt_f2h<<<(3 * DIMC * DIMC / 4 + 255) / 256, 256>>>(w_qkv, p_wq,
                                                            3 * DIMC * DIMC / 4);
        cvt_f2h<<<(DIMC * DIMC / 4 + 255) / 256, 256>>>(w_proj, p_wp,
                                                        DIMC * DIMC / 4);
    }

    // 1) fused QKV projection -> fp16 g_qh/g_kh/g_vh
    dim3 g1(1536 / 256, NTOK / 128);
    hgemm<0><<<g1, 512, GEMM_SMEM>>>(nullptr, nullptr);

    // 2) HMMA attention -> fp16 g_oh
    attn_tc<<<BH, 256, ATTN_SMEM>>>();

    // 3) output projection + bias -> fp32 d_out
    dim3 g2(512 / 256, NTOK / 128);
    hgemm<1><<<g2, 512, GEMM_SMEM>>>(out, b_proj);
}

// round 6
// speedup vs baseline: 5.5321x; 1.0439x over previous
#include <cuda_runtime.h>
#include <cuda_fp16.h>
#include <cstdint>

// Problem constants
#define DIMC   512
#define HEADS  8
#define WIN    128
#define HD     64
#define NTOK   65536          // 16*4096
#define NWIN   512            // NTOK/WIN
#define BH     (NWIN*HEADS)   // 4096

// Scratch (device globals)
__device__ __half hx[(size_t)NTOK * DIMC];        // fp16 copy of x
__device__ __half hwqkv[(size_t)3 * DIMC * DIMC]; // fp16 w_qkv
__device__ __half hwproj[(size_t)DIMC * DIMC];    // fp16 w_proj
__device__ __half g_qh[(size_t)BH * WIN * HD];    // fp16 q [win,h,t,d]
__device__ __half g_kh[(size_t)BH * WIN * HD];
__device__ __half g_vh[(size_t)BH * WIN * HD];
__device__ __half g_oh[(size_t)NTOK * DIMC];      // fp16 attention output

// ---------------------------------------------------------------------------
// helpers
// ---------------------------------------------------------------------------
__device__ __forceinline__ uint32_t s2u(const void* p) {
    uint32_t a;
    asm("{ .reg .u64 t; cvta.to.shared.u64 t, %1; cvt.u32.u64 %0, t; }"
        : "=r"(a) : "l"(p));
    return a;
}

__device__ __forceinline__ void cp16(uint32_t dst, const void* src) {
    asm volatile("cp.async.cg.shared.global [%0], [%1], 16;" :: "r"(dst), "l"(src));
}
#define CP_COMMIT() asm volatile("cp.async.commit_group;" ::: "memory")

__device__ __forceinline__ void ldsm_x4(uint32_t* r, uint32_t a) {
    asm volatile("ldmatrix.sync.aligned.m8n8.x4.shared.b16 {%0,%1,%2,%3}, [%4];"
        : "=r"(r[0]), "=r"(r[1]), "=r"(r[2]), "=r"(r[3]) : "r"(a));
}

__device__ __forceinline__ void ldsm_x4t(uint32_t* r, uint32_t a) {
    asm volatile("ldmatrix.sync.aligned.m8n8.x4.trans.shared.b16 {%0,%1,%2,%3}, [%4];"
        : "=r"(r[0]), "=r"(r[1]), "=r"(r[2]), "=r"(r[3]) : "r"(a));
}

__device__ __forceinline__ void mma_f16(float* d, const uint32_t* a,
                                        const uint32_t b0, const uint32_t b1) {
    asm volatile(
        "mma.sync.aligned.m16n8k16.row.col.f32.f16.f16.f32 "
        "{%0,%1,%2,%3}, {%4,%5,%6,%7}, {%8,%9}, {%0,%1,%2,%3};"
        : "+f"(d[0]), "+f"(d[1]), "+f"(d[2]), "+f"(d[3])
        : "r"(a[0]), "r"(a[1]), "r"(a[2]), "r"(a[3]), "r"(b0), "r"(b1));
}

__device__ __forceinline__ uint32_t packh2(float x, float y) {
    __half2 h = __floats2half2_rn(x, y);
    return *(uint32_t*)&h;
}

// ---------------------------------------------------------------------------
// fp32 -> fp16 conversion
// ---------------------------------------------------------------------------
__global__ void cvt_f2h(const float* __restrict__ src, __half* __restrict__ dst,
                        int n4)
{
    int i = blockIdx.x * blockDim.x + threadIdx.x;
    if (i < n4) {
        float4 v = ((const float4*)src)[i];
        ((__half2*)dst)[2 * i]     = __floats2half2_rn(v.x, v.y);
        ((__half2*)dst)[2 * i + 1] = __floats2half2_rn(v.z, v.w);
    }
}

// ---------------------------------------------------------------------------
// fp16 HMMA GEMM: C[m,n] = sum_k A[m,k]*B[n,k], K=512.
// Block tile 128x128, BK=64, 3-stage cp.async, 256 threads / 8 warps,
// warp tile 32x64. 110.6 KB smem -> 2 CTAs/SM (two barrier domains).
// MODE 0: A=hx, B=hwqkv -> fp16 scatter into g_qh/g_kh/g_vh [win,h,t,d]
// MODE 1: A=g_oh, B=hwproj, +bias -> fp32 C
// ---------------------------------------------------------------------------
#define T_STG 18432                          // 128 rows * 144 B (one matrix)
#define STG   (2 * T_STG)                    // 36864 per stage
#define GEMM_SMEM (3 * STG)                  // 110592

template<int MODE>
__global__ void __launch_bounds__(256, 2)
hgemm(float* __restrict__ C, const float* __restrict__ bias)
{
    extern __shared__ __align__(128) char smem[];
    const __half* Ag = (MODE == 0) ? hx : g_oh;
    const __half* Bg = (MODE == 0) ? hwqkv : hwproj;

    const uint32_t sb = s2u(smem);
    const int tid  = threadIdx.x;
    const int m0   = blockIdx.y * 128;
    const int n0   = blockIdx.x * 128;
    const int warp = tid >> 5, lane = tid & 31;
    const int wy   = warp >> 1, wx = warp & 1;   // warp tile: (wy*32, wx*64)

    float acc[16][4];                            // [mt*8+nt]
#pragma unroll
    for (int i = 0; i < 16; ++i)
#pragma unroll
        for (int j = 0; j < 4; ++j) acc[i][j] = 0.0f;

    const int lrow = tid >> 3;                   // 0..31
    const int lc   = tid & 7;

#define LOAD_STAGE(kt, s)                                                      \
    do {                                                                       \
        const uint32_t sa_  = sb + (s) * STG;                                  \
        const uint32_t sb2_ = sa_ + T_STG;                                     \
        _Pragma("unroll")                                                      \
        for (int u = 0; u < 4; ++u) {                                          \
            const int row = lrow + u * 32;                                     \
            cp16(sa_ + row * 144 + lc * 16,                                    \
                 Ag + (size_t)(m0 + row) * 512 + (kt) * 64 + lc * 8);          \
            cp16(sb2_ + row * 144 + lc * 16,                                   \
                 Bg + (size_t)(n0 + row) * 512 + (kt) * 64 + lc * 8);          \
        }                                                                      \
        CP_COMMIT();                                                           \
    } while (0)

    LOAD_STAGE(0, 0);
    LOAD_STAGE(1, 1);

    for (int kt = 0; kt < 8; ++kt) {
        if (kt == 7)
            asm volatile("cp.async.wait_group 0;" ::: "memory");
        else
            asm volatile("cp.async.wait_group 1;" ::: "memory");
        __syncthreads();

        if (kt + 2 < 8) LOAD_STAGE(kt + 2, (kt + 2) % 3);

        const uint32_t sa_  = sb + (kt % 3) * STG;
        const uint32_t sb2_ = sa_ + T_STG;

#pragma unroll
        for (int ks = 0; ks < 4; ++ks) {
            const int col = ks * 16 + ((lane >> 4) << 3);
            uint32_t af[2][4], bf[4][4];
#pragma unroll
            for (int mt = 0; mt < 2; ++mt) {
                const int row = wy * 32 + mt * 16 + (lane & 15);
                ldsm_x4(af[mt], sa_ + row * 144 + col * 2);
            }
#pragma unroll
            for (int np = 0; np < 4; ++np) {
                const int row =
                    wx * 64 + np * 16 + (lane & 7) + ((lane >> 3) & 1) * 8;
                ldsm_x4(bf[np], sb2_ + row * 144 + col * 2);
            }
#pragma unroll
            for (int mt = 0; mt < 2; ++mt)
#pragma unroll
                for (int nt = 0; nt < 8; ++nt)
                    mma_f16(acc[mt * 8 + nt], af[mt],
                            bf[nt >> 1][nt & 1], bf[nt >> 1][(nt & 1) + 2]);
        }
    }
#undef LOAD_STAGE

    // epilogue
#pragma unroll
    for (int mt = 0; mt < 2; ++mt) {
#pragma unroll
        for (int nt = 0; nt < 8; ++nt) {
            const int m = m0 + wy * 32 + mt * 16 + (lane >> 2);
            const int n = n0 + wx * 64 + nt * 8 + ((lane & 3) << 1);
            const float* a = acc[mt * 8 + nt];
            if (MODE == 0) {
                const int sidx = n >> 9;
                const int h    = (n >> 6) & 7;
                const int d    = n & 63;
                __half* dst = (sidx == 0) ? g_qh : ((sidx == 1) ? g_kh : g_vh);
                const int win = m >> 7;
                const size_t b0i =
                    (((size_t)(win * HEADS + h)) * WIN + (m & 127)) * HD + d;
                const size_t b1i = b0i + 8 * HD;
                *(uint32_t*)&dst[b0i] = packh2(a[0], a[1]);
                *(uint32_t*)&dst[b1i] = packh2(a[2], a[3]);
            } else {
                const float2 bv = *(const float2*)&bias[n];
                *(float2*)&C[(size_t)m * 512 + n] =
                    make_float2(a[0] + bv.x, a[1] + bv.y);
                *(float2*)&C[(size_t)(m + 8) * 512 + n] =
                    make_float2(a[2] + bv.x, a[3] + bv.y);
            }
        }
    }
}

// ---------------------------------------------------------------------------
// HMMA attention: one CTA per (window, head), 256 threads / 8 warps.
// Warp w owns query rows [w*16, w*16+16). S = Q K^T (fp32 accum), register
// softmax, P fragment reused directly for P*V.
// ---------------------------------------------------------------------------
#define APAD 144                             // bytes per smem row (72 halfs)
#define ATILE (128 * APAD)                   // 18432
#define ATTN_SMEM (3 * ATILE)                // 55296

__global__ void __launch_bounds__(256, 2)
attn_tc()
{
    extern __shared__ __align__(128) char smem[];
    const uint32_t sQ = s2u(smem);
    const uint32_t sK = sQ + ATILE;
    const uint32_t sV = sK + ATILE;

    const int bh   = blockIdx.x;
    const int tid  = threadIdx.x;
    const int warp = tid >> 5, lane = tid & 31;

    const __half* qg = g_qh + (size_t)bh * (WIN * HD);
    const __half* kg = g_kh + (size_t)bh * (WIN * HD);
    const __half* vg = g_vh + (size_t)bh * (WIN * HD);

#pragma unroll
    for (int u = 0; u < 4; ++u) {
        const int id  = tid + u * 256;
        const int row = id >> 3, c = id & 7;
        const uint32_t off = row * APAD + c * 16;
        cp16(sQ + off, qg + row * 64 + c * 8);
        cp16(sK + off, kg + row * 64 + c * 8);
        cp16(sV + off, vg + row * 64 + c * 8);
    }
    CP_COMMIT();
    asm volatile("cp.async.wait_group 0;" ::: "memory");
    __syncthreads();

    // ---- S = Q K^T : per warp 16 x 128, fp32 accum ----
    float sacc[16][4];
#pragma unroll
    for (int i = 0; i < 16; ++i)
#pragma unroll
        for (int j = 0; j < 4; ++j) sacc[i][j] = 0.0f;

#pragma unroll
    for (int ks = 0; ks < 4; ++ks) {
        const int col = ks * 16 + ((lane >> 4) << 3);
        uint32_t af[4];
        {
            const int row = warp * 16 + (lane & 15);
            ldsm_x4(af, sQ + row * APAD + col * 2);
        }
#pragma unroll
        for (int np = 0; np < 8; ++np) {
            uint32_t bf[4];
            const int row = np * 16 + (lane & 7) + ((lane >> 3) & 1) * 8;
            ldsm_x4(bf, sK + row * APAD + col * 2);
            mma_f16(sacc[np * 2 + 0], af, bf[0], bf[2]);
            mma_f16(sacc[np * 2 + 1], af, bf[1], bf[3]);
        }
    }

    // ---- causal mask + softmax in registers ----
    const int rlo = warp * 16 + (lane >> 2);
    const int rhi = rlo + 8;
    float mx0 = -1e30f, mx1 = -1e30f;
#pragma unroll
    for (int nt = 0; nt < 16; ++nt) {
        const int cb = nt * 8 + ((lane & 3) << 1);
        float s0 = sacc[nt][0] * 0.125f;
        float s1 = sacc[nt][1] * 0.125f;
        float s2 = sacc[nt][2] * 0.125f;
        float s3 = sacc[nt][3] * 0.125f;
        if (cb     > rlo) s0 = -1e30f;
        if (cb + 1 > rlo) s1 = -1e30f;
        if (cb     > rhi) s2 = -1e30f;
        if (cb + 1 > rhi) s3 = -1e30f;
        sacc[nt][0] = s0; sacc[nt][1] = s1;
        sacc[nt][2] = s2; sacc[nt][3] = s3;
        mx0 = fmaxf(mx0, fmaxf(s0, s1));
        mx1 = fmaxf(mx1, fmaxf(s2, s3));
    }
    mx0 = fmaxf(mx0, __shfl_xor_sync(0xffffffffu, mx0, 1));
    mx0 = fmaxf(mx0, __shfl_xor_sync(0xffffffffu, mx0, 2));
    mx1 = fmaxf(mx1, __shfl_xor_sync(0xffffffffu, mx1, 1));
    mx1 = fmaxf(mx1, __shfl_xor_sync(0xffffffffu, mx1, 2));

    float sum0 = 0.0f, sum1 = 0.0f;
#pragma unroll
    for (int nt = 0; nt < 16; ++nt) {
        float e0 = __expf(sacc[nt][0] - mx0);
        float e1 = __expf(sacc[nt][1] - mx0);
        float e2 = __expf(sacc[nt][2] - mx1);
        float e3 = __expf(sacc[nt][3] - mx1);
        sacc[nt][0] = e0; sacc[nt][1] = e1;
        sacc[nt][2] = e2; sacc[nt][3] = e3;
        sum0 += e0 + e1;
        sum1 += e2 + e3;
    }
    sum0 += __shfl_xor_sync(0xffffffffu, sum0, 1);
    sum0 += __shfl_xor_sync(0xffffffffu, sum0, 2);
    sum1 += __shfl_xor_sync(0xffffffffu, sum1, 1);
    sum1 += __shfl_xor_sync(0xffffffffu, sum1, 2);
    const float inv0 = 1.0f / sum0;
    const float inv1 = 1.0f / sum1;

    // ---- O = P V : per warp 16 x 64 ----
    float oacc[8][4];
#pragma unroll
    for (int i = 0; i < 8; ++i)
#pragma unroll
        for (int j = 0; j < 4; ++j) oacc[i][j] = 0.0f;

#pragma unroll
    for (int kt = 0; kt < 8; ++kt) {
        uint32_t ap[4];
        ap[0] = packh2(sacc[2 * kt][0] * inv0,     sacc[2 * kt][1] * inv0);
        ap[1] = packh2(sacc[2 * kt][2] * inv1,     sacc[2 * kt][3] * inv1);
        ap[2] = packh2(sacc[2 * kt + 1][0] * inv0, sacc[2 * kt + 1][1] * inv0);
        ap[3] = packh2(sacc[2 * kt + 1][2] * inv1, sacc[2 * kt + 1][3] * inv1);

#pragma unroll
        for (int nb = 0; nb < 4; ++nb) {
            uint32_t bv[4];
            const int row = kt * 16 + (lane & 15);
            const int col = nb * 16 + ((lane >> 4) << 3);
            ldsm_x4t(bv, sV + row * APAD + col * 2);
            mma_f16(oacc[nb * 2 + 0], ap, bv[0], bv[1]);
            mma_f16(oacc[nb * 2 + 1], ap, bv[2], bv[3]);
        }
    }

    // ---- write O to g_oh [token][C] fp16 ----
    const int win = bh >> 3, h = bh & 7;
    const size_t row_lo = (size_t)(win * WIN + warp * 16 + (lane >> 2)) * DIMC
                          + h * HD + ((lane & 3) << 1);
#pragma unroll
    for (int nt = 0; nt < 8; ++nt) {
        *(uint32_t*)&g_oh[row_lo + nt * 8]            = packh2(oacc[nt][0], oacc[nt][1]);
        *(uint32_t*)&g_oh[row_lo + 8 * DIMC + nt * 8] = packh2(oacc[nt][2], oacc[nt][3]);
    }
}

// ---------------------------------------------------------------------------
extern "C" void kernel_launch(void* const* d_in, const int* in_sizes, int n_in,
                              void* d_out, int out_size)
{
    const float* x      = (const float*)d_in[0];  // [16,4096,512]
    const float* w_qkv  = (const float*)d_in[1];  // [1536,512]
    const float* w_proj = (const float*)d_in[2];  // [512,512]
    const float* b_proj = (const float*)d_in[3];  // [512]
    float* out = (float*)d_out;                   // [16,4096,512]

    cudaFuncSetAttribute(hgemm<0>, cudaFuncAttributeMaxDynamicSharedMemorySize,
                         GEMM_SMEM);
    cudaFuncSetAttribute(hgemm<1>, cudaFuncAttributeMaxDynamicSharedMemorySize,
                         GEMM_SMEM);
    cudaFuncSetAttribute(hgemm<0>,
                         cudaFuncAttributePreferredSharedMemoryCarveout, 100);
    cudaFuncSetAttribute(hgemm<1>,
                         cudaFuncAttributePreferredSharedMemoryCarveout, 100);
    cudaFuncSetAttribute(attn_tc, cudaFuncAttributeMaxDynamicSharedMemorySize,
                         ATTN_SMEM);

    // 0) fp32 -> fp16 conversions
    {
        __half* p_hx = nullptr;  __half* p_wq = nullptr;  __half* p_wp = nullptr;
        cudaGetSymbolAddress((void**)&p_hx, hx);
        cudaGetSymbolAddress((void**)&p_wq, hwqkv);
        cudaGetSymbolAddress((void**)&p_wp, hwproj);
        cvt_f2h<<<(NTOK * DIMC / 4 + 255) / 256, 256>>>(x, p_hx, NTOK * DIMC / 4);
        cvt_f2h<<<(3 * DIMC * DIMC / 4 + 255) / 256, 256>>>(w_qkv, p_wq,
                                                            3 * DIMC * DIMC / 4);
        cvt_f2h<<<(DIMC * DIMC / 4 + 255) / 256, 256>>>(w_proj, p_wp,
                                                        DIMC * DIMC / 4);
    }

    // 1) fused QKV projection -> fp16 g_qh/g_kh/g_vh
    dim3 g1(1536 / 128, NTOK / 128);
    hgemm<0><<<g1, 256, GEMM_SMEM>>>(nullptr, nullptr);

    // 2) HMMA attention -> fp16 g_oh
    attn_tc<<<BH, 256, ATTN_SMEM>>>();

    // 3) output projection + bias -> fp32 d_out
    dim3 g2(512 / 128, NTOK / 128);
    hgemm<1><<<g2, 256, GEMM_SMEM>>>(out, b_proj);
}

// round 7
// speedup vs baseline: 6.0602x; 1.0955x over previous
#include <cuda_runtime.h>
#include <cuda_fp16.h>
#include <cstdint>

// Problem constants
#define DIMC   512
#define HEADS  8
#define WIN    128
#define HD     64
#define NTOK   65536          // 16*4096
#define NWIN   512            // NTOK/WIN
#define BH     (NWIN*HEADS)   // 4096

// Scratch (device globals)
__device__ __half hx[(size_t)NTOK * DIMC];        // fp16 copy of x
__device__ __half hwqkv[(size_t)3 * DIMC * DIMC]; // fp16 w_qkv
__device__ __half hwproj[(size_t)DIMC * DIMC];    // fp16 w_proj
__device__ __half g_qh[(size_t)BH * WIN * HD];    // fp16 q [win,h,t,d]
__device__ __half g_kh[(size_t)BH * WIN * HD];
__device__ __half g_vh[(size_t)BH * WIN * HD];
__device__ __half g_oh[(size_t)NTOK * DIMC];      // fp16 attention output

// ---------------------------------------------------------------------------
// helpers
// ---------------------------------------------------------------------------
__device__ __forceinline__ uint32_t s2u(const void* p) {
    uint32_t a;
    asm("{ .reg .u64 t; cvta.to.shared.u64 t, %1; cvt.u32.u64 %0, t; }"
        : "=r"(a) : "l"(p));
    return a;
}

__device__ __forceinline__ void cp16(uint32_t dst, const void* src) {
    asm volatile("cp.async.cg.shared.global [%0], [%1], 16;" :: "r"(dst), "l"(src));
}
#define CP_COMMIT() asm volatile("cp.async.commit_group;" ::: "memory")

__device__ __forceinline__ void ldsm_x4(uint32_t* r, uint32_t a) {
    asm volatile("ldmatrix.sync.aligned.m8n8.x4.shared.b16 {%0,%1,%2,%3}, [%4];"
        : "=r"(r[0]), "=r"(r[1]), "=r"(r[2]), "=r"(r[3]) : "r"(a));
}

__device__ __forceinline__ void ldsm_x4t(uint32_t* r, uint32_t a) {
    asm volatile("ldmatrix.sync.aligned.m8n8.x4.trans.shared.b16 {%0,%1,%2,%3}, [%4];"
        : "=r"(r[0]), "=r"(r[1]), "=r"(r[2]), "=r"(r[3]) : "r"(a));
}

__device__ __forceinline__ void mma_f16(float* d, const uint32_t* a,
                                        const uint32_t b0, const uint32_t b1) {
    asm volatile(
        "mma.sync.aligned.m16n8k16.row.col.f32.f16.f16.f32 "
        "{%0,%1,%2,%3}, {%4,%5,%6,%7}, {%8,%9}, {%0,%1,%2,%3};"
        : "+f"(d[0]), "+f"(d[1]), "+f"(d[2]), "+f"(d[3])
        : "r"(a[0]), "r"(a[1]), "r"(a[2]), "r"(a[3]), "r"(b0), "r"(b1));
}

__device__ __forceinline__ uint32_t packh2(float x, float y) {
    __half2 h = __floats2half2_rn(x, y);
    return *(uint32_t*)&h;
}

// ---------------------------------------------------------------------------
// merged fp32 -> fp16 conversion for x, w_qkv, w_proj (one launch)
// ---------------------------------------------------------------------------
#define N4_X   (NTOK * DIMC / 4)             // 8388608
#define N4_WQ  (3 * DIMC * DIMC / 4)         // 196608
#define N4_WP  (DIMC * DIMC / 4)             // 65536
#define N4_ALL (N4_X + N4_WQ + N4_WP)

__global__ void cvt_all(const float* __restrict__ x,
                        const float* __restrict__ wq,
                        const float* __restrict__ wp)
{
    int i = blockIdx.x * blockDim.x + threadIdx.x;
    if (i >= N4_ALL) return;
    const float* src;
    __half* dst;
    int j;
    if (i < N4_X)              { src = x;  dst = hx;     j = i; }
    else if (i < N4_X + N4_WQ) { src = wq; dst = hwqkv;  j = i - N4_X; }
    else                       { src = wp; dst = hwproj; j = i - N4_X - N4_WQ; }
    float4 v = ((const float4*)src)[j];
    ((__half2*)dst)[2 * j]     = __floats2half2_rn(v.x, v.y);
    ((__half2*)dst)[2 * j + 1] = __floats2half2_rn(v.z, v.w);
}

// ---------------------------------------------------------------------------
// fp16 HMMA GEMM: C[m,n] = sum_k A[m,k]*B[n,k], K=512.
// Block tile 128x128, BK=64, 3-stage cp.async, 256 threads / 8 warps,
// warp tile 32x64, 2 CTAs/SM. Fragment software pipelining: ldmatrix for
// sub-step ks+1 is issued before the MMAs of ks (double-buffered frags).
// MODE 0: A=hx, B=hwqkv -> fp16 scatter into g_qh/g_kh/g_vh [win,h,t,d]
// MODE 1: A=g_oh, B=hwproj, +bias -> fp32 C
// ---------------------------------------------------------------------------
#define T_STG 18432                          // 128 rows * 144 B (one matrix)
#define STG   (2 * T_STG)                    // 36864 per stage
#define GEMM_SMEM (3 * STG)                  // 110592

template<int MODE>
__global__ void __launch_bounds__(256, 2)
hgemm(float* __restrict__ C, const float* __restrict__ bias)
{
    extern __shared__ __align__(128) char smem[];
    const __half* Ag = (MODE == 0) ? hx : g_oh;
    const __half* Bg = (MODE == 0) ? hwqkv : hwproj;

    const uint32_t sb = s2u(smem);
    const int tid  = threadIdx.x;
    const int m0   = blockIdx.y * 128;
    const int n0   = blockIdx.x * 128;
    const int warp = tid >> 5, lane = tid & 31;
    const int wy   = warp >> 1, wx = warp & 1;   // warp tile: (wy*32, wx*64)

    float acc[16][4];                            // [mt*8+nt]
#pragma unroll
    for (int i = 0; i < 16; ++i)
#pragma unroll
        for (int j = 0; j < 4; ++j) acc[i][j] = 0.0f;

    const int lrow = tid >> 3;                   // 0..31
    const int lc   = tid & 7;

    // per-warp ldmatrix row offsets (byte offsets within a tile)
    const uint32_t a_off0 = (wy * 32 +      (lane & 15)) * 144;
    const uint32_t a_off1 = (wy * 32 + 16 + (lane & 15)) * 144;
    const uint32_t colb   = ((lane >> 4) << 3) * 2;      // 0 or 16 bytes
    uint32_t b_off[4];
#pragma unroll
    for (int np = 0; np < 4; ++np)
        b_off[np] = (uint32_t)(wx * 64 + np * 16 + (lane & 7) +
                               ((lane >> 3) & 1) * 8) * 144;

#define LOAD_STAGE(kt, s)                                                      \
    do {                                                                       \
        const uint32_t sa_  = sb + (s) * STG;                                  \
        const uint32_t sb2_ = sa_ + T_STG;                                     \
        _Pragma("unroll")                                                      \
        for (int u = 0; u < 4; ++u) {                                          \
            const int row = lrow + u * 32;                                     \
            cp16(sa_ + row * 144 + lc * 16,                                    \
                 Ag + (size_t)(m0 + row) * 512 + (kt) * 64 + lc * 8);          \
            cp16(sb2_ + row * 144 + lc * 16,                                   \
                 Bg + (size_t)(n0 + row) * 512 + (kt) * 64 + lc * 8);          \
        }                                                                      \
        CP_COMMIT();                                                           \
    } while (0)

// issue all 6 ldmatrix for sub-step `ks` into buffer slot `bi`
#define LDSM_KS(ks, bi, saq, sbq)                                              \
    do {                                                                       \
        const uint32_t cb_ = (ks) * 32 + colb;                                 \
        ldsm_x4(af[bi][0], (saq) + a_off0 + cb_);                              \
        ldsm_x4(af[bi][1], (saq) + a_off1 + cb_);                              \
        ldsm_x4(bf[bi][0], (sbq) + b_off[0] + cb_);                            \
        ldsm_x4(bf[bi][1], (sbq) + b_off[1] + cb_);                            \
        ldsm_x4(bf[bi][2], (sbq) + b_off[2] + cb_);                            \
        ldsm_x4(bf[bi][3], (sbq) + b_off[3] + cb_);                            \
    } while (0)

#define MMA_KS(bi)                                                             \
    do {                                                                       \
        _Pragma("unroll")                                                      \
        for (int mt = 0; mt < 2; ++mt)                                         \
            _Pragma("unroll")                                                  \
            for (int nt = 0; nt < 8; ++nt)                                     \
                mma_f16(acc[mt * 8 + nt], af[bi][mt],                          \
                        bf[bi][nt >> 1][nt & 1], bf[bi][nt >> 1][(nt & 1) + 2]);\
    } while (0)

    LOAD_STAGE(0, 0);
    LOAD_STAGE(1, 1);

    uint32_t af[2][2][4], bf[2][4][4];

#pragma unroll
    for (int kt = 0; kt < 8; ++kt) {
        if (kt == 7)
            asm volatile("cp.async.wait_group 0;" ::: "memory");
        else
            asm volatile("cp.async.wait_group 1;" ::: "memory");
        __syncthreads();

        if (kt + 2 < 8) LOAD_STAGE(kt + 2, (kt + 2) % 3);

        const uint32_t sa_  = sb + (kt % 3) * STG;
        const uint32_t sb2_ = sa_ + T_STG;

        LDSM_KS(0, 0, sa_, sb2_);
#pragma unroll
        for (int ks = 0; ks < 4; ++ks) {
            const int cur = ks & 1, nxt = cur ^ 1;
            if (ks < 3) LDSM_KS(ks + 1, nxt, sa_, sb2_);
            MMA_KS(cur);
        }
    }
#undef LOAD_STAGE
#undef LDSM_KS
#undef MMA_KS

    // epilogue
#pragma unroll
    for (int mt = 0; mt < 2; ++mt) {
#pragma unroll
        for (int nt = 0; nt < 8; ++nt) {
            const int m = m0 + wy * 32 + mt * 16 + (lane >> 2);
            const int n = n0 + wx * 64 + nt * 8 + ((lane & 3) << 1);
            const float* a = acc[mt * 8 + nt];
            if (MODE == 0) {
                const int sidx = n >> 9;
                const int h    = (n >> 6) & 7;
                const int d    = n & 63;
                __half* dst = (sidx == 0) ? g_qh : ((sidx == 1) ? g_kh : g_vh);
                const int win = m >> 7;
                const size_t b0i =
                    (((size_t)(win * HEADS + h)) * WIN + (m & 127)) * HD + d;
                const size_t b1i = b0i + 8 * HD;
                *(uint32_t*)&dst[b0i] = packh2(a[0], a[1]);
                *(uint32_t*)&dst[b1i] = packh2(a[2], a[3]);
            } else {
                const float2 bv = *(const float2*)&bias[n];
                *(float2*)&C[(size_t)m * 512 + n] =
                    make_float2(a[0] + bv.x, a[1] + bv.y);
                *(float2*)&C[(size_t)(m + 8) * 512 + n] =
                    make_float2(a[2] + bv.x, a[3] + bv.y);
            }
        }
    }
}

// ---------------------------------------------------------------------------
// HMMA attention: one CTA per (window, head), 256 threads / 8 warps.
// ---------------------------------------------------------------------------
#define APAD 144                             // bytes per smem row (72 halfs)
#define ATILE (128 * APAD)                   // 18432
#define ATTN_SMEM (3 * ATILE)                // 55296

__global__ void __launch_bounds__(256, 2)
attn_tc()
{
    extern __shared__ __align__(128) char smem[];
    const uint32_t sQ = s2u(smem);
    const uint32_t sK = sQ + ATILE;
    const uint32_t sV = sK + ATILE;

    const int bh   = blockIdx.x;
    const int tid  = threadIdx.x;
    const int warp = tid >> 5, lane = tid & 31;

    const __half* qg = g_qh + (size_t)bh * (WIN * HD);
    const __half* kg = g_kh + (size_t)bh * (WIN * HD);
    const __half* vg = g_vh + (size_t)bh * (WIN * HD);

#pragma unroll
    for (int u = 0; u < 4; ++u) {
        const int id  = tid + u * 256;
        const int row = id >> 3, c = id & 7;
        const uint32_t off = row * APAD + c * 16;
        cp16(sQ + off, qg + row * 64 + c * 8);
        cp16(sK + off, kg + row * 64 + c * 8);
        cp16(sV + off, vg + row * 64 + c * 8);
    }
    CP_COMMIT();
    asm volatile("cp.async.wait_group 0;" ::: "memory");
    __syncthreads();

    // ---- S = Q K^T : per warp 16 x 128, fp32 accum ----
    float sacc[16][4];
#pragma unroll
    for (int i = 0; i < 16; ++i)
#pragma unroll
        for (int j = 0; j < 4; ++j) sacc[i][j] = 0.0f;

#pragma unroll
    for (int ks = 0; ks < 4; ++ks) {
        const int col = ks * 16 + ((lane >> 4) << 3);
        uint32_t af[4];
        {
            const int row = warp * 16 + (lane & 15);
            ldsm_x4(af, sQ + row * APAD + col * 2);
        }
#pragma unroll
        for (int np = 0; np < 8; ++np) {
            uint32_t bf[4];
            const int row = np * 16 + (lane & 7) + ((lane >> 3) & 1) * 8;
            ldsm_x4(bf, sK + row * APAD + col * 2);
            mma_f16(sacc[np * 2 + 0], af, bf[0], bf[2]);
            mma_f16(sacc[np * 2 + 1], af, bf[1], bf[3]);
        }
    }

    // ---- causal mask + softmax in registers ----
    const int rlo = warp * 16 + (lane >> 2);
    const int rhi = rlo + 8;
    float mx0 = -1e30f, mx1 = -1e30f;
#pragma unroll
    for (int nt = 0; nt < 16; ++nt) {
        const int cb = nt * 8 + ((lane & 3) << 1);
        float s0 = sacc[nt][0] * 0.125f;
        float s1 = sacc[nt][1] * 0.125f;
        float s2 = sacc[nt][2] * 0.125f;
        float s3 = sacc[nt][3] * 0.125f;
        if (cb     > rlo) s0 = -1e30f;
        if (cb + 1 > rlo) s1 = -1e30f;
        if (cb     > rhi) s2 = -1e30f;
        if (cb + 1 > rhi) s3 = -1e30f;
        sacc[nt][0] = s0; sacc[nt][1] = s1;
        sacc[nt][2] = s2; sacc[nt][3] = s3;
        mx0 = fmaxf(mx0, fmaxf(s0, s1));
        mx1 = fmaxf(mx1, fmaxf(s2, s3));
    }
    mx0 = fmaxf(mx0, __shfl_xor_sync(0xffffffffu, mx0, 1));
    mx0 = fmaxf(mx0, __shfl_xor_sync(0xffffffffu, mx0, 2));
    mx1 = fmaxf(mx1, __shfl_xor_sync(0xffffffffu, mx1, 1));
    mx1 = fmaxf(mx1, __shfl_xor_sync(0xffffffffu, mx1, 2));

    float sum0 = 0.0f, sum1 = 0.0f;
#pragma unroll
    for (int nt = 0; nt < 16; ++nt) {
        float e0 = __expf(sacc[nt][0] - mx0);
        float e1 = __expf(sacc[nt][1] - mx0);
        float e2 = __expf(sacc[nt][2] - mx1);
        float e3 = __expf(sacc[nt][3] - mx1);
        sacc[nt][0] = e0; sacc[nt][1] = e1;
        sacc[nt][2] = e2; sacc[nt][3] = e3;
        sum0 += e0 + e1;
        sum1 += e2 + e3;
    }
    sum0 += __shfl_xor_sync(0xffffffffu, sum0, 1);
    sum0 += __shfl_xor_sync(0xffffffffu, sum0, 2);
    sum1 += __shfl_xor_sync(0xffffffffu, sum1, 1);
    sum1 += __shfl_xor_sync(0xffffffffu, sum1, 2);
    const float inv0 = 1.0f / sum0;
    const float inv1 = 1.0f / sum1;

    // ---- O = P V : per warp 16 x 64 ----
    float oacc[8][4];
#pragma unroll
    for (int i = 0; i < 8; ++i)
#pragma unroll
        for (int j = 0; j < 4; ++j) oacc[i][j] = 0.0f;

#pragma unroll
    for (int kt = 0; kt < 8; ++kt) {
        uint32_t ap[4];
        ap[0] = packh2(sacc[2 * kt][0] * inv0,     sacc[2 * kt][1] * inv0);
        ap[1] = packh2(sacc[2 * kt][2] * inv1,     sacc[2 * kt][3] * inv1);
        ap[2] = packh2(sacc[2 * kt + 1][0] * inv0, sacc[2 * kt + 1][1] * inv0);
        ap[3] = packh2(sacc[2 * kt + 1][2] * inv1, sacc[2 * kt + 1][3] * inv1);

#pragma unroll
        for (int nb = 0; nb < 4; ++nb) {
            uint32_t bv[4];
            const int row = kt * 16 + (lane & 15);
            const int col = nb * 16 + ((lane >> 4) << 3);
            ldsm_x4t(bv, sV + row * APAD + col * 2);
            mma_f16(oacc[nb * 2 + 0], ap, bv[0], bv[1]);
            mma_f16(oacc[nb * 2 + 1], ap, bv[2], bv[3]);
        }
    }

    // ---- write O to g_oh [token][C] fp16 ----
    const int win = bh >> 3, h = bh & 7;
    const size_t row_lo = (size_t)(win * WIN + warp * 16 + (lane >> 2)) * DIMC
                          + h * HD + ((lane & 3) << 1);
#pragma unroll
    for (int nt = 0; nt < 8; ++nt) {
        *(uint32_t*)&g_oh[row_lo + nt * 8]            = packh2(oacc[nt][0], oacc[nt][1]);
        *(uint32_t*)&g_oh[row_lo + 8 * DIMC + nt * 8] = packh2(oacc[nt][2], oacc[nt][3]);
    }
}

// ---------------------------------------------------------------------------
extern "C" void kernel_launch(void* const* d_in, const int* in_sizes, int n_in,
                              void* d_out, int out_size)
{
    const float* x      = (const float*)d_in[0];  // [16,4096,512]
    const float* w_qkv  = (const float*)d_in[1];  // [1536,512]
    const float* w_proj = (const float*)d_in[2];  // [512,512]
    const float* b_proj = (const float*)d_in[3];  // [512]
    float* out = (float*)d_out;                   // [16,4096,512]

    cudaFuncSetAttribute(hgemm<0>, cudaFuncAttributeMaxDynamicSharedMemorySize,
                         GEMM_SMEM);
    cudaFuncSetAttribute(hgemm<1>, cudaFuncAttributeMaxDynamicSharedMemorySize,
                         GEMM_SMEM);
    cudaFuncSetAttribute(hgemm<0>,
                         cudaFuncAttributePreferredSharedMemoryCarveout, 100);
    cudaFuncSetAttribute(hgemm<1>,
                         cudaFuncAttributePreferredSharedMemoryCarveout, 100);
    cudaFuncSetAttribute(attn_tc, cudaFuncAttributeMaxDynamicSharedMemorySize,
                         ATTN_SMEM);
    cudaFuncSetAttribute(attn_tc,
                         cudaFuncAttributePreferredSharedMemoryCarveout, 100);

    // 0) fp32 -> fp16 conversions (single launch)
    cvt_all<<<(N4_ALL + 255) / 256, 256>>>(x, w_qkv, w_proj);

    // 1) fused QKV projection -> fp16 g_qh/g_kh/g_vh
    dim3 g1(1536 / 128, NTOK / 128);
    hgemm<0><<<g1, 256, GEMM_SMEM>>>(nullptr, nullptr);

    // 2) HMMA attention -> fp16 g_oh
    attn_tc<<<BH, 256, ATTN_SMEM>>>();

    // 3) output projection + bias -> fp32 d_out
    dim3 g2(512 / 128, NTOK / 128);
    hgemm<1><<<g2, 256, GEMM_SMEM>>>(out, b_proj);
}